// round 10
// baseline (speedup 1.0000x reference)
#include <cuda_runtime.h>
#include <cuda_fp16.h>
#include <cstdint>
#include <math.h>

// Problem dims (fixed)
#define BB 4
#define SS 4096
#define DD 1024
#define AA 1024
#define MTOT (BB*SS)   // 16384

// int8 split scales (Q,K elem ~N(0,1.6)): hi covers +-9, lo covers +-2e-3
#define SH   (9.0f/127.0f)
#define SL   (2.0e-3f/127.0f)
#define ISH  (127.0f/9.0f)
#define ISL  (127.0f/2.0e-3f)
#define SC   (SH*SL)

// ---------------------------------------------------------------------------
// Device scratch
// ---------------------------------------------------------------------------
__device__ float g_Vf[(size_t)MTOT * AA];                 // 64 MB
__device__ float g_S [(size_t)BB * SS * SS];              // 256 MB scores
__device__ __half g_Xhi[(size_t)MTOT * DD];
__device__ __half g_Xlo[(size_t)MTOT * DD];
__device__ __half g_Wh[3][(size_t)AA * DD];               // (16*W)^T splits [A,D]
__device__ __half g_Wl[3][(size_t)AA * DD];
__device__ __half g_Qhi[(size_t)MTOT * AA];
__device__ __half g_Khi[(size_t)MTOT * AA];
__device__ signed char g_Q8h[(size_t)MTOT * AA];          // int8, k-permuted
__device__ signed char g_Q8l[(size_t)MTOT * AA];
__device__ signed char g_K8h[(size_t)MTOT * AA];
__device__ signed char g_K8l[(size_t)MTOT * AA];
__device__ __half g_Vthi[(size_t)BB * AA * SS];           // V^T per batch [A,S]
__device__ __half g_Phi[(size_t)BB * SS * SS];            // 128 MB

// ---------------------------------------------------------------------------
// Helpers
// ---------------------------------------------------------------------------
__device__ __forceinline__ uint32_t smem_u32(const void* p) {
    uint32_t a;
    asm("{ .reg .u64 t; cvta.to.shared.u64 t, %1; cvt.u32.u64 %0, t; }" : "=r"(a) : "l"(p));
    return a;
}

#define CP_ASYNC16(saddr, gaddr) \
    asm volatile("cp.async.cg.shared.global [%0], [%1], 16;" :: "r"(saddr), "l"(gaddr))
#define CP_COMMIT()  asm volatile("cp.async.commit_group;" ::: "memory")
#define CP_WAIT1()   asm volatile("cp.async.wait_group 1;" ::: "memory")
#define CP_WAIT0()   asm volatile("cp.async.wait_group 0;" ::: "memory")

#define MMA_F16(c, a, b) \
    asm volatile("mma.sync.aligned.m16n8k16.row.col.f32.f16.f16.f32 " \
        "{%0,%1,%2,%3}, {%4,%5,%6,%7}, {%8,%9}, {%0,%1,%2,%3};" \
        : "+f"((c)[0]), "+f"((c)[1]), "+f"((c)[2]), "+f"((c)[3]) \
        : "r"((a)[0]), "r"((a)[1]), "r"((a)[2]), "r"((a)[3]), \
          "r"((b)[0]), "r"((b)[1]))

// int8 MMA, k=32 per instruction (2x the MACs of HMMA k16)
#define MMA_S8(c, a, b) \
    asm volatile("mma.sync.aligned.m16n8k32.row.col.s32.s8.s8.s32 " \
        "{%0,%1,%2,%3}, {%4,%5,%6,%7}, {%8,%9}, {%0,%1,%2,%3};" \
        : "+r"((c)[0]), "+r"((c)[1]), "+r"((c)[2]), "+r"((c)[3]) \
        : "r"((a)[0]), "r"((a)[1]), "r"((a)[2]), "r"((a)[3]), \
          "r"((b)[0]), "r"((b)[1]))

#define LDS64(r0, r1, addr) \
    asm volatile("ld.shared.v2.b32 {%0,%1}, [%2];" : "=r"(r0), "=r"(r1) : "r"(addr))

// permuted int8 column: within each 32-k block, byte for logical k goes to
// 8*(k>>2 & 3) + 4*(k>>4) + (k&3), so one LDS.64 at offset 8*kq yields the
// IMMA fragment pair {k=4kq..4kq+3, k=4kq+16..+19}.
__device__ __forceinline__ int perm_col(int col) {
    return (col & ~31) + ((col >> 2) & 3) * 8 + ((col >> 4) & 1) * 4 + (col & 3);
}
__device__ __forceinline__ signed char quant8(float v, float inv_s) {
    float t = fminf(fmaxf(v * inv_s, -127.0f), 127.0f);
    return (signed char)__float2int_rn(t);
}

// ---------------------------------------------------------------------------
// HMMA GEMM, fp16 hi/lo split, term count NT (all f32-accumulate):
//   NT=3: AhBh + AlBh + AhBl ; NT=1: AhBh
// SPLIT_OUT epilogue writes fp16 hi + k-permuted int8 hi/lo (for QK^T).
// CTA 128x128, KC=32, 2-stage, 2 CTAs/SM, warp tile 32x64.
// ---------------------------------------------------------------------------
#define KC    32
#define ROWB  80                              // 32 fp16 (64B) + 16B pad
#define TILE_T (128 * ROWB)                   // 10240 B

__device__ __forceinline__ void load_tile32(const __half* __restrict__ g,
                                            int ldK, char* sb, int tid)
{
#pragma unroll
    for (int i = 0; i < 2; i++) {
        int ch = tid + i * 256;
        int row = ch >> 2, c = ch & 3;
        CP_ASYNC16(smem_u32(sb + row * ROWB + c * 16),
                   g + (size_t)row * ldK + c * 8);
    }
}

template <int NT>
__device__ __forceinline__ void load_stage(const __half* pAh, const __half* pAl,
                                           const __half* pBh, const __half* pBl,
                                           int k0, int K, char* sp, int tid)
{
    load_tile32(pAh + k0, K, sp, tid);
    if (NT == 3) {
        load_tile32(pAl + k0, K, sp + TILE_T,     tid);
        load_tile32(pBh + k0, K, sp + 2 * TILE_T, tid);
        load_tile32(pBl + k0, K, sp + 3 * TILE_T, tid);
    } else {
        load_tile32(pBh + k0, K, sp + TILE_T, tid);
    }
    CP_COMMIT();
}

template <int NT, bool SPLIT_OUT>
__global__ __launch_bounds__(256, 2)
void gemm_mma(const __half* __restrict__ Ahi, const __half* __restrict__ Alo,
              const __half* __restrict__ Bhi, const __half* __restrict__ Blo,
              float* __restrict__ C,
              __half* __restrict__ Chi,
              signed char* __restrict__ C8h, signed char* __restrict__ C8l,
              int K, int ldC,
              long long sA, long long sB, long long sC, float oscale)
{
    constexpr int STG = (NT == 3 ? 4 : 2) * TILE_T;
    extern __shared__ __align__(128) char smem[];
    const int tid = threadIdx.x;
    const int wid = tid >> 5, lane = tid & 31;
    const int wm = wid & 3, wn = wid >> 2;    // 4(m) x 2(n)
    const int m0 = blockIdx.y * 128;
    const int n0 = blockIdx.x * 128;

    const __half* pAh = Ahi + (size_t)blockIdx.z * sA + (size_t)m0 * K;
    const __half* pAl = (NT == 3) ? Alo + (size_t)blockIdx.z * sA + (size_t)m0 * K : nullptr;
    const __half* pBh = Bhi + (size_t)blockIdx.z * sB + (size_t)n0 * K;
    const __half* pBl = (NT == 3) ? Blo + (size_t)blockIdx.z * sB + (size_t)n0 * K : nullptr;

    float acc[2][8][4];
#pragma unroll
    for (int mt = 0; mt < 2; mt++)
#pragma unroll
        for (int nt = 0; nt < 8; nt++)
#pragma unroll
            for (int j = 0; j < 4; j++) acc[mt][nt][j] = 0.0f;

    const int nch = K >> 5;

    load_stage<NT>(pAh, pAl, pBh, pBl, 0,  K, smem,       tid);
    load_stage<NT>(pAh, pAl, pBh, pBl, KC, K, smem + STG, tid);

    const int r  = lane >> 2;
    const int kq = lane & 3;

    for (int c = 0; c < nch; ++c) {
        if (c + 1 < nch) CP_WAIT1(); else CP_WAIT0();
        __syncthreads();

        const char* sp  = smem + (c & 1) * STG;
        const char* sAh = sp;
        const char* sAl = sp + TILE_T;
        const char* sBh = sp + (NT == 3 ? 2 : 1) * TILE_T;
        const char* sBl = sp + 3 * TILE_T;

#pragma unroll
        for (int ks = 0; ks < 2; ++ks) {
            const int kb = ks * 32 + kq * 4;

            uint32_t ah[2][4], al[2][4];
#pragma unroll
            for (int mt = 0; mt < 2; mt++) {
                const int row = wm * 32 + mt * 16 + r;
                const char* a0 = sAh + row * ROWB + kb;
                const char* a1 = sAh + (row + 8) * ROWB + kb;
                ah[mt][0] = *(const uint32_t*)(a0);
                ah[mt][1] = *(const uint32_t*)(a1);
                ah[mt][2] = *(const uint32_t*)(a0 + 16);
                ah[mt][3] = *(const uint32_t*)(a1 + 16);
                if (NT == 3) {
                    const char* b0 = sAl + row * ROWB + kb;
                    const char* b1 = sAl + (row + 8) * ROWB + kb;
                    al[mt][0] = *(const uint32_t*)(b0);
                    al[mt][1] = *(const uint32_t*)(b1);
                    al[mt][2] = *(const uint32_t*)(b0 + 16);
                    al[mt][3] = *(const uint32_t*)(b1 + 16);
                }
            }
#pragma unroll
            for (int nt = 0; nt < 8; nt++) {
                const int n = wn * 64 + nt * 8 + r;
                uint32_t bh[2];
                const char* p = sBh + n * ROWB + kb;
                bh[0] = *(const uint32_t*)(p);
                bh[1] = *(const uint32_t*)(p + 16);
#pragma unroll
                for (int mt = 0; mt < 2; mt++) {
                    MMA_F16(acc[mt][nt], ah[mt], bh);
                    if (NT == 3) MMA_F16(acc[mt][nt], al[mt], bh);
                }
                if (NT == 3) {
                    uint32_t bl[2];
                    const char* q = sBl + n * ROWB + kb;
                    bl[0] = *(const uint32_t*)(q);
                    bl[1] = *(const uint32_t*)(q + 16);
#pragma unroll
                    for (int mt = 0; mt < 2; mt++)
                        MMA_F16(acc[mt][nt], ah[mt], bl);
                }
            }
        }

        if (c + 2 < nch) {
            __syncthreads();
            load_stage<NT>(pAh, pAl, pBh, pBl, (c + 2) * KC, K,
                           smem + (c & 1) * STG, tid);
        }
    }

    // epilogue
    const int cq = (lane & 3) * 2;
    if (!SPLIT_OUT) {
        float* Cw = C + (size_t)blockIdx.z * sC
                      + (size_t)(m0 + wm * 32) * ldC + n0 + wn * 64;
#pragma unroll
        for (int mt = 0; mt < 2; mt++)
#pragma unroll
            for (int nt = 0; nt < 8; nt++) {
                float* p0 = Cw + (size_t)(mt * 16 + r) * ldC + nt * 8 + cq;
                float* p1 = p0 + 8 * (size_t)ldC;
                *(float2*)p0 = make_float2(acc[mt][nt][0] * oscale, acc[mt][nt][1] * oscale);
                *(float2*)p1 = make_float2(acc[mt][nt][2] * oscale, acc[mt][nt][3] * oscale);
            }
    } else {
        // write fp16 hi + permuted int8 hi/lo
#pragma unroll
        for (int mt = 0; mt < 2; mt++)
#pragma unroll
            for (int nt = 0; nt < 8; nt++) {
                const int col = n0 + wn * 64 + nt * 8 + cq;
                const int pc  = perm_col(col);
                const size_t row0 = (size_t)(m0 + wm * 32 + mt * 16 + r);
                const size_t row1 = row0 + 8;
                float x0 = acc[mt][nt][0] * oscale, x1 = acc[mt][nt][1] * oscale;
                float x2 = acc[mt][nt][2] * oscale, x3 = acc[mt][nt][3] * oscale;
                __half h0 = __float2half_rn(x0), h1 = __float2half_rn(x1);
                __half h2 = __float2half_rn(x2), h3 = __float2half_rn(x3);
                *(__half2*)(Chi + row0 * ldC + col) = __halves2half2(h0, h1);
                *(__half2*)(Chi + row1 * ldC + col) = __halves2half2(h2, h3);
                float l0 = x0 - __half2float(h0), l1 = x1 - __half2float(h1);
                float l2 = x2 - __half2float(h2), l3 = x3 - __half2float(h3);
                char2 v8;
                v8.x = quant8(x0, ISH); v8.y = quant8(x1, ISH);
                *(char2*)(C8h + row0 * ldC + pc) = v8;
                v8.x = quant8(x2, ISH); v8.y = quant8(x3, ISH);
                *(char2*)(C8h + row1 * ldC + pc) = v8;
                v8.x = quant8(l0, ISL); v8.y = quant8(l1, ISL);
                *(char2*)(C8l + row0 * ldC + pc) = v8;
                v8.x = quant8(l2, ISL); v8.y = quant8(l3, ISL);
                *(char2*)(C8l + row1 * ldC + pc) = v8;
            }
    }
}

// ---------------------------------------------------------------------------
// QK^T kernel: main term fp16 HMMA (Qh*Kh), corrections via int8 IMMA k32
// (Q8l*K8h + Q8h*K8l into one shared s32 accumulator; scale SC).
// CTA 128(m) x 64(n), 8 warps 4m x 2n, warp tile 32x32. 2-stage, 2 CTA/SM.
// ---------------------------------------------------------------------------
#define QK_QH   0
#define QK_KH   10240
#define QK_Q8L  15360
#define QK_Q8H  19456
#define QK_K8H  23552
#define QK_K8L  25600
#define QK_STG  27648

__device__ __forceinline__ void load_stage_qk(
    const __half* qh, const __half* kh,
    const signed char* q8l, const signed char* q8h,
    const signed char* k8h, const signed char* k8l,
    int k0, char* sp, int tid)
{
    load_tile32(qh + k0, AA, sp + QK_QH, tid);
    { int row = tid >> 2, c = tid & 3;
      CP_ASYNC16(smem_u32(sp + QK_KH + row * ROWB + c * 16),
                 kh + k0 + (size_t)row * AA + c * 8); }
    { int row = tid >> 1, h = tid & 1;
      CP_ASYNC16(smem_u32(sp + QK_Q8L + row * 32 + h * 16),
                 q8l + k0 + (size_t)row * AA + h * 16); }
    { int row = tid >> 1, h = tid & 1;
      CP_ASYNC16(smem_u32(sp + QK_Q8H + row * 32 + h * 16),
                 q8h + k0 + (size_t)row * AA + h * 16); }
    if (tid < 128) {
        int row = tid >> 1, h = tid & 1;
        CP_ASYNC16(smem_u32(sp + QK_K8H + row * 32 + h * 16),
                   k8h + k0 + (size_t)row * AA + h * 16);
    } else {
        int t2 = tid - 128; int row = t2 >> 1, h = t2 & 1;
        CP_ASYNC16(smem_u32(sp + QK_K8L + row * 32 + h * 16),
                   k8l + k0 + (size_t)row * AA + h * 16);
    }
    CP_COMMIT();
}

__global__ __launch_bounds__(256, 2)
void qk_imma(const __half* __restrict__ Qh, const __half* __restrict__ Kh,
             const signed char* __restrict__ Q8l, const signed char* __restrict__ Q8h,
             const signed char* __restrict__ K8h, const signed char* __restrict__ K8l,
             float* __restrict__ S)
{
    extern __shared__ __align__(128) char smem[];
    const int tid = threadIdx.x;
    const int wid = tid >> 5, lane = tid & 31;
    const int wm = wid & 3, wn = wid >> 2;     // 4m x 2n
    const int m0 = blockIdx.y * 128;
    const int n0 = blockIdx.x * 64;
    const size_t zoff = (size_t)blockIdx.z * SS * AA;

    const __half* pQh = Qh + zoff + (size_t)m0 * AA;
    const __half* pKh = Kh + zoff + (size_t)n0 * AA;
    const signed char* pQ8l = Q8l + zoff + (size_t)m0 * AA;
    const signed char* pQ8h = Q8h + zoff + (size_t)m0 * AA;
    const signed char* pK8h = K8h + zoff + (size_t)n0 * AA;
    const signed char* pK8l = K8l + zoff + (size_t)n0 * AA;

    float acc[2][4][4];
    int   icc[2][4][4];
#pragma unroll
    for (int mt = 0; mt < 2; mt++)
#pragma unroll
        for (int nt = 0; nt < 4; nt++)
#pragma unroll
            for (int j = 0; j < 4; j++) { acc[mt][nt][j] = 0.0f; icc[mt][nt][j] = 0; }

    const int nch = AA >> 5;   // 32
    load_stage_qk(pQh, pKh, pQ8l, pQ8h, pK8h, pK8l, 0,  smem,          tid);
    load_stage_qk(pQh, pKh, pQ8l, pQ8h, pK8h, pK8l, KC, smem + QK_STG, tid);

    const int r  = lane >> 2;
    const int kq = lane & 3;

    for (int c = 0; c < nch; ++c) {
        if (c + 1 < nch) CP_WAIT1(); else CP_WAIT0();
        __syncthreads();

        const char* sp   = smem + (c & 1) * QK_STG;
        const char* sQh  = sp + QK_QH;
        const char* sKh  = sp + QK_KH;
        const char* sQ8l = sp + QK_Q8L;
        const char* sQ8h = sp + QK_Q8H;
        const char* sK8h = sp + QK_K8H;
        const char* sK8l = sp + QK_K8L;

        // int8 A fragments (cover full k=32 chunk)
        uint32_t a8l[2][4], a8h[2][4];
#pragma unroll
        for (int mt = 0; mt < 2; mt++) {
            const int R = wm * 32 + mt * 16 + r;
            uint32_t ad = smem_u32(sQ8l + R * 32 + kq * 8);
            LDS64(a8l[mt][0], a8l[mt][2], ad);
            LDS64(a8l[mt][1], a8l[mt][3], ad + 8 * 32);
            ad = smem_u32(sQ8h + R * 32 + kq * 8);
            LDS64(a8h[mt][0], a8h[mt][2], ad);
            LDS64(a8h[mt][1], a8h[mt][3], ad + 8 * 32);
        }

        // fp16 main term
#pragma unroll
        for (int ks = 0; ks < 2; ++ks) {
            const int kb = ks * 32 + kq * 4;
            uint32_t ah[2][4];
#pragma unroll
            for (int mt = 0; mt < 2; mt++) {
                const int row = wm * 32 + mt * 16 + r;
                const char* a0 = sQh + row * ROWB + kb;
                const char* a1 = sQh + (row + 8) * ROWB + kb;
                ah[mt][0] = *(const uint32_t*)(a0);
                ah[mt][1] = *(const uint32_t*)(a1);
                ah[mt][2] = *(const uint32_t*)(a0 + 16);
                ah[mt][3] = *(const uint32_t*)(a1 + 16);
            }
#pragma unroll
            for (int nt = 0; nt < 4; nt++) {
                const int n = wn * 32 + nt * 8 + r;
                uint32_t bh[2];
                const char* p = sKh + n * ROWB + kb;
                bh[0] = *(const uint32_t*)(p);
                bh[1] = *(const uint32_t*)(p + 16);
#pragma unroll
                for (int mt = 0; mt < 2; mt++)
                    MMA_F16(acc[mt][nt], ah[mt], bh);
            }
        }

        // int8 corrections (k=32 per IMMA)
#pragma unroll
        for (int nt = 0; nt < 4; nt++) {
            const int n = wn * 32 + nt * 8 + r;
            uint32_t b8h[2], b8l[2];
            LDS64(b8h[0], b8h[1], smem_u32(sK8h + n * 32 + kq * 8));
            LDS64(b8l[0], b8l[1], smem_u32(sK8l + n * 32 + kq * 8));
#pragma unroll
            for (int mt = 0; mt < 2; mt++) {
                MMA_S8(icc[mt][nt], a8l[mt], b8h);
                MMA_S8(icc[mt][nt], a8h[mt], b8l);
            }
        }

        if (c + 2 < nch) {
            __syncthreads();
            load_stage_qk(pQh, pKh, pQ8l, pQ8h, pK8h, pK8l, (c + 2) * KC,
                          smem + (c & 1) * QK_STG, tid);
        }
    }

    // epilogue: fold int corrections, write fp32 scores
    const int cq = (lane & 3) * 2;
    float* Sw = S + (size_t)blockIdx.z * SS * SS
                  + (size_t)(m0 + wm * 32) * SS + n0 + wn * 32;
#pragma unroll
    for (int mt = 0; mt < 2; mt++)
#pragma unroll
        for (int nt = 0; nt < 4; nt++) {
            float* p0 = Sw + (size_t)(mt * 16 + r) * SS + nt * 8 + cq;
            float* p1 = p0 + 8 * (size_t)SS;
            *(float2*)p0 = make_float2(acc[mt][nt][0] + (float)icc[mt][nt][0] * SC,
                                       acc[mt][nt][1] + (float)icc[mt][nt][1] * SC);
            *(float2*)p1 = make_float2(acc[mt][nt][2] + (float)icc[mt][nt][2] * SC,
                                       acc[mt][nt][3] + (float)icc[mt][nt][3] * SC);
        }
}

// ---------------------------------------------------------------------------
// fp32 -> fp16 hi/lo split (elementwise)
// ---------------------------------------------------------------------------
__global__ __launch_bounds__(256)
void split_plain(const float* __restrict__ in, __half* __restrict__ hi,
                 __half* __restrict__ lo, size_t n)
{
    size_t i = ((size_t)blockIdx.x * 256 + threadIdx.x) * 4;
    if (i >= n) return;
    float4 x = *(const float4*)(in + i);
    __half h0 = __float2half_rn(x.x), h1 = __float2half_rn(x.y);
    __half h2 = __float2half_rn(x.z), h3 = __float2half_rn(x.w);
    __half l0 = __float2half_rn(x.x - __half2float(h0));
    __half l1 = __float2half_rn(x.y - __half2float(h1));
    __half l2 = __float2half_rn(x.z - __half2float(h2));
    __half l3 = __float2half_rn(x.w - __half2float(h3));
    *(__half2*)(hi + i)     = __halves2half2(h0, h1);
    *(__half2*)(hi + i + 2) = __halves2half2(h2, h3);
    *(__half2*)(lo + i)     = __halves2half2(l0, l1);
    *(__half2*)(lo + i + 2) = __halves2half2(l2, l3);
}

// ---------------------------------------------------------------------------
// fp32 [R,C] -> transposed, scaled fp16 hi/lo [C,R]
// ---------------------------------------------------------------------------
__global__ __launch_bounds__(256)
void transpose_split(const float* __restrict__ in, __half* __restrict__ hiT,
                     __half* __restrict__ loT, int R, int C, float scale)
{
    __shared__ float t[32][33];
    const int r0 = blockIdx.y * 32, c0 = blockIdx.x * 32;
    const int tx = threadIdx.x & 31, ty = threadIdx.x >> 5;
#pragma unroll
    for (int i = ty; i < 32; i += 8)
        t[i][tx] = in[(size_t)(r0 + i) * C + c0 + tx];
    __syncthreads();
#pragma unroll
    for (int i = ty; i < 32; i += 8) {
        float x = t[tx][i] * scale;
        __half h = __float2half_rn(x);
        __half l = __float2half_rn(x - __half2float(h));
        size_t o = (size_t)(c0 + i) * R + r0 + tx;
        hiT[o] = h; loT[o] = l;
    }
}

// fp32 [R,C] -> transposed fp16 hi only [C,R] (batched via z)
__global__ __launch_bounds__(256)
void transpose_hi(const float* __restrict__ in, __half* __restrict__ hiT,
                  int R, int C, long long sIn, long long sOut)
{
    __shared__ float t[32][33];
    in  += (size_t)blockIdx.z * sIn;
    hiT += (size_t)blockIdx.z * sOut;
    const int r0 = blockIdx.y * 32, c0 = blockIdx.x * 32;
    const int tx = threadIdx.x & 31, ty = threadIdx.x >> 5;
#pragma unroll
    for (int i = ty; i < 32; i += 8)
        t[i][tx] = in[(size_t)(r0 + i) * C + c0 + tx];
    __syncthreads();
#pragma unroll
    for (int i = ty; i < 32; i += 8)
        hiT[(size_t)(c0 + i) * R + r0 + tx] = __float2half_rn(t[tx][i]);
}

// ---------------------------------------------------------------------------
// Row softmax (4096 cols), write fp16 (hi only)
// ---------------------------------------------------------------------------
__global__ __launch_bounds__(256)
void softmax_f16(const float* __restrict__ S, __half* __restrict__ Ph)
{
    const size_t row = blockIdx.x;
    const float* p = S + row * (size_t)SS;
    const int tid = threadIdx.x;

    float4 v[4];
    float m = -INFINITY;
#pragma unroll
    for (int i = 0; i < 4; i++) {
        v[i] = ((const float4*)p)[tid + i * 256];
        m = fmaxf(m, fmaxf(fmaxf(v[i].x, v[i].y), fmaxf(v[i].z, v[i].w)));
    }
    __shared__ float red[256];
    red[tid] = m; __syncthreads();
#pragma unroll
    for (int s = 128; s > 0; s >>= 1) {
        if (tid < s) red[tid] = fmaxf(red[tid], red[tid + s]);
        __syncthreads();
    }
    const float rowmax = red[0];
    __syncthreads();

    float sum = 0.0f;
#pragma unroll
    for (int i = 0; i < 4; i++) {
        v[i].x = __expf(v[i].x - rowmax);
        v[i].y = __expf(v[i].y - rowmax);
        v[i].z = __expf(v[i].z - rowmax);
        v[i].w = __expf(v[i].w - rowmax);
        sum += v[i].x + v[i].y + v[i].z + v[i].w;
    }
    red[tid] = sum; __syncthreads();
#pragma unroll
    for (int s = 128; s > 0; s >>= 1) {
        if (tid < s) red[tid] += red[tid + s];
        __syncthreads();
    }
    const float inv = 1.0f / red[0];
    __syncthreads();

#pragma unroll
    for (int i = 0; i < 4; i++) {
        size_t o = row * (size_t)SS + (size_t)(tid + i * 256) * 4;
        *(__half2*)(Ph + o)     = __halves2half2(__float2half_rn(v[i].x * inv),
                                                 __float2half_rn(v[i].y * inv));
        *(__half2*)(Ph + o + 2) = __halves2half2(__float2half_rn(v[i].z * inv),
                                                 __float2half_rn(v[i].w * inv));
    }
}

// ---------------------------------------------------------------------------
// kernel_launch — graph-capturable pipeline
// ---------------------------------------------------------------------------
extern "C" void kernel_launch(void* const* d_in, const int* in_sizes, int n_in,
                              void* d_out, int out_size)
{
    const float* X  = (const float*)d_in[0];
    const float* Wq = (const float*)d_in[1];
    const float* Wk = (const float*)d_in[2];
    const float* Wv = (const float*)d_in[3];
    float* out = (float*)d_out;

    float *Vf, *Sc;
    __half *Xhi, *Xlo, *Wh, *Wl, *Qhi, *Khi, *Vthi, *Phi;
    signed char *Q8h, *Q8l, *K8h, *K8l;
    cudaGetSymbolAddress((void**)&Vf, g_Vf);
    cudaGetSymbolAddress((void**)&Sc, g_S);
    cudaGetSymbolAddress((void**)&Xhi, g_Xhi);
    cudaGetSymbolAddress((void**)&Xlo, g_Xlo);
    cudaGetSymbolAddress((void**)&Wh, g_Wh);
    cudaGetSymbolAddress((void**)&Wl, g_Wl);
    cudaGetSymbolAddress((void**)&Qhi, g_Qhi);
    cudaGetSymbolAddress((void**)&Khi, g_Khi);
    cudaGetSymbolAddress((void**)&Q8h, g_Q8h);
    cudaGetSymbolAddress((void**)&Q8l, g_Q8l);
    cudaGetSymbolAddress((void**)&K8h, g_K8h);
    cudaGetSymbolAddress((void**)&K8l, g_K8l);
    cudaGetSymbolAddress((void**)&Vthi, g_Vthi);
    cudaGetSymbolAddress((void**)&Phi, g_Phi);

    const int SMEM_NT3 = 2 * 4 * TILE_T;   // 81920
    const int SMEM_NT1 = 2 * 2 * TILE_T;   // 40960
    const int SMEM_QK  = 2 * QK_STG;       // 55296
    cudaFuncSetAttribute(gemm_mma<3,false>, cudaFuncAttributeMaxDynamicSharedMemorySize, SMEM_NT3);
    cudaFuncSetAttribute(gemm_mma<3,true>,  cudaFuncAttributeMaxDynamicSharedMemorySize, SMEM_NT3);
    cudaFuncSetAttribute(gemm_mma<1,false>, cudaFuncAttributeMaxDynamicSharedMemorySize, SMEM_NT1);
    cudaFuncSetAttribute(qk_imma,           cudaFuncAttributeMaxDynamicSharedMemorySize, SMEM_QK);

    const size_t WSZ = (size_t)AA * DD;
    const float WS = 16.0f, INV_WS = 1.0f / 16.0f;

    // 1) split X; transpose+split the three weight matrices (scaled by 16)
    split_plain<<<(MTOT * (size_t)DD) / 1024, 256>>>(X, Xhi, Xlo, (size_t)MTOT * DD);
    {
        dim3 g(AA / 32, DD / 32, 1);
        transpose_split<<<g, 256>>>(Wq, Wh + 0 * WSZ, Wl + 0 * WSZ, DD, AA, WS);
        transpose_split<<<g, 256>>>(Wk, Wh + 1 * WSZ, Wl + 1 * WSZ, DD, AA, WS);
        transpose_split<<<g, 256>>>(Wv, Wh + 2 * WSZ, Wl + 2 * WSZ, DD, AA, WS);
    }

    // 2) projections: Q,K 3-term -> fp16 hi + int8 hi/lo (permuted); V 1-term
    {
        dim3 g(AA / 128, MTOT / 128, 1);
        gemm_mma<3,true><<<g, 256, SMEM_NT3>>>(Xhi, Xlo, Wh + 0*WSZ, Wl + 0*WSZ,
                                               nullptr, Qhi, Q8h, Q8l,
                                               DD, AA, 0, 0, 0, INV_WS);
        gemm_mma<3,true><<<g, 256, SMEM_NT3>>>(Xhi, Xlo, Wh + 1*WSZ, Wl + 1*WSZ,
                                               nullptr, Khi, K8h, K8l,
                                               DD, AA, 0, 0, 0, INV_WS);
        gemm_mma<1,false><<<g, 256, SMEM_NT1>>>(Xhi, nullptr, Wh + 2*WSZ, nullptr,
                                                Vf, nullptr, nullptr, nullptr,
                                                DD, AA, 0, 0, 0, INV_WS);
    }

    // 3) transpose V per batch to fp16 [A,S], hi only
    {
        dim3 g(AA / 32, SS / 32, BB);
        transpose_hi<<<g, 256>>>(Vf, Vthi, SS, AA,
                                 (long long)SS * AA, (long long)SS * AA);
    }

    // 4) scores: main fp16 HMMA + int8 IMMA corrections
    {
        dim3 g(SS / 64, SS / 128, BB);
        qk_imma<<<g, 256, SMEM_QK>>>(Qhi, Khi, Q8l, Q8h, K8h, K8l, Sc);
    }

    // 5) softmax -> fp16 P (hi only)
    softmax_f16<<<BB * SS, 256>>>(Sc, Phi);

    // 6) output (1-term): O = P @ V per batch
    {
        dim3 g(AA / 128, SS / 128, BB);
        gemm_mma<1,false><<<g, 256, SMEM_NT1>>>(Phi, nullptr, Vthi, nullptr,
                                                out, nullptr, nullptr, nullptr,
                                                SS, AA,
                                                (long long)SS * SS, (long long)AA * SS,
                                                (long long)SS * AA, 1.0f);
    }
}

// round 11
// speedup vs baseline: 1.7032x; 1.7032x over previous
#include <cuda_runtime.h>
#include <cuda_fp16.h>
#include <cstdint>
#include <math.h>

// Problem dims (fixed)
#define BB 4
#define SS 4096
#define DD 1024
#define AA 1024
#define MTOT (BB*SS)   // 16384

// ---------------------------------------------------------------------------
// Device scratch
// ---------------------------------------------------------------------------
__device__ float g_S [(size_t)BB * SS * SS];              // 256 MB scores
__device__ __half g_Vh[(size_t)MTOT * AA];                // V projection, fp16
__device__ __half g_Xhi[(size_t)MTOT * DD];
__device__ __half g_Xlo[(size_t)MTOT * DD];
__device__ __half g_Wh[3][(size_t)AA * DD];               // (16*W)^T splits [A,D]
__device__ __half g_Wl[3][(size_t)AA * DD];
__device__ __half g_Qhi[(size_t)MTOT * AA];
__device__ __half g_Qlo[(size_t)MTOT * AA];
__device__ __half g_Khi[(size_t)MTOT * AA];
__device__ __half g_Klo[(size_t)MTOT * AA];
__device__ __half g_Vthi[(size_t)BB * AA * SS];           // V^T per batch [A,S]
__device__ __half g_Phi[(size_t)BB * SS * SS];            // 128 MB

// ---------------------------------------------------------------------------
// Helpers
// ---------------------------------------------------------------------------
__device__ __forceinline__ uint32_t smem_u32(const void* p) {
    uint32_t a;
    asm("{ .reg .u64 t; cvta.to.shared.u64 t, %1; cvt.u32.u64 %0, t; }" : "=r"(a) : "l"(p));
    return a;
}

#define CP_ASYNC16(saddr, gaddr) \
    asm volatile("cp.async.cg.shared.global [%0], [%1], 16;" :: "r"(saddr), "l"(gaddr))
#define CP_COMMIT()  asm volatile("cp.async.commit_group;" ::: "memory")
#define CP_WAIT1()   asm volatile("cp.async.wait_group 1;" ::: "memory")
#define CP_WAIT0()   asm volatile("cp.async.wait_group 0;" ::: "memory")

#define MMA_F16(c, a, b) \
    asm volatile("mma.sync.aligned.m16n8k16.row.col.f32.f16.f16.f32 " \
        "{%0,%1,%2,%3}, {%4,%5,%6,%7}, {%8,%9}, {%0,%1,%2,%3};" \
        : "+f"((c)[0]), "+f"((c)[1]), "+f"((c)[2]), "+f"((c)[3]) \
        : "r"((a)[0]), "r"((a)[1]), "r"((a)[2]), "r"((a)[3]), \
          "r"((b)[0]), "r"((b)[1]))

// ---------------------------------------------------------------------------
// HMMA GEMM, fp16 hi/lo split, term count NT (all f32-accumulate):
//   NT=3: AhBh + AlBh + AhBl   (A split, B split)
//   NT=1: AhBh                 (A hi, B hi)
// OUT: 0 = fp32 C; 1 = fp16 hi/lo pair (Chi,Clo); 2 = fp16 hi only (Chi)
// C[M,N] = A[M,K] * B[N,K]^T, K-major. CTA tile 128x128, KC=32,
// 2-stage cp.async double buffer, 2 CTAs/SM.
// 8 warps as 4(m) x 2(n); warp tile 32x64 = 2 m16 x 8 n8 mma tiles.
// ---------------------------------------------------------------------------
#define KC    32
#define ROWB  80                              // 32 fp16 (64B) + 16B pad
#define TILE_T (128 * ROWB)                   // 10240 B

__device__ __forceinline__ void load_tile32(const __half* __restrict__ g,
                                            int ldK, char* sb, int tid)
{
#pragma unroll
    for (int i = 0; i < 2; i++) {
        int ch = tid + i * 256;               // 0..511
        int row = ch >> 2, c = ch & 3;
        CP_ASYNC16(smem_u32(sb + row * ROWB + c * 16),
                   g + (size_t)row * ldK + c * 8);
    }
}

template <int NT>
__device__ __forceinline__ void load_stage(const __half* pAh, const __half* pAl,
                                           const __half* pBh, const __half* pBl,
                                           int k0, int K, char* sp, int tid)
{
    load_tile32(pAh + k0, K, sp, tid);
    if (NT == 3) {
        load_tile32(pAl + k0, K, sp + TILE_T,     tid);
        load_tile32(pBh + k0, K, sp + 2 * TILE_T, tid);
        load_tile32(pBl + k0, K, sp + 3 * TILE_T, tid);
    } else {
        load_tile32(pBh + k0, K, sp + TILE_T, tid);
    }
    CP_COMMIT();
}

template <int NT, int OUT>
__global__ __launch_bounds__(256, 2)
void gemm_mma(const __half* __restrict__ Ahi, const __half* __restrict__ Alo,
              const __half* __restrict__ Bhi, const __half* __restrict__ Blo,
              float* __restrict__ C,
              __half* __restrict__ Chi, __half* __restrict__ Clo,
              int K, int ldC,
              long long sA, long long sB, long long sC, float oscale)
{
    constexpr int STG = (NT == 3 ? 4 : 2) * TILE_T;
    extern __shared__ __align__(128) char smem[];
    const int tid = threadIdx.x;
    const int wid = tid >> 5, lane = tid & 31;
    const int wm = wid & 3, wn = wid >> 2;    // 4(m) x 2(n)
    const int m0 = blockIdx.y * 128;
    const int n0 = blockIdx.x * 128;

    const __half* pAh = Ahi + (size_t)blockIdx.z * sA + (size_t)m0 * K;
    const __half* pAl = (NT == 3) ? Alo + (size_t)blockIdx.z * sA + (size_t)m0 * K : nullptr;
    const __half* pBh = Bhi + (size_t)blockIdx.z * sB + (size_t)n0 * K;
    const __half* pBl = (NT == 3) ? Blo + (size_t)blockIdx.z * sB + (size_t)n0 * K : nullptr;

    float acc[2][8][4];
#pragma unroll
    for (int mt = 0; mt < 2; mt++)
#pragma unroll
        for (int nt = 0; nt < 8; nt++)
#pragma unroll
            for (int j = 0; j < 4; j++) acc[mt][nt][j] = 0.0f;

    const int nch = K >> 5;

    load_stage<NT>(pAh, pAl, pBh, pBl, 0,  K, smem,       tid);
    load_stage<NT>(pAh, pAl, pBh, pBl, KC, K, smem + STG, tid);

    const int r  = lane >> 2;        // 0..7
    const int kq = lane & 3;         // 0..3

    for (int c = 0; c < nch; ++c) {
        if (c + 1 < nch) CP_WAIT1(); else CP_WAIT0();
        __syncthreads();

        const char* sp  = smem + (c & 1) * STG;
        const char* sAh = sp;
        const char* sAl = sp + TILE_T;                       // NT==3
        const char* sBh = sp + (NT == 3 ? 2 : 1) * TILE_T;
        const char* sBl = sp + 3 * TILE_T;                   // NT==3

#pragma unroll
        for (int ks = 0; ks < 2; ++ks) {
            const int kb = ks * 32 + kq * 4;

            uint32_t ah[2][4], al[2][4];
#pragma unroll
            for (int mt = 0; mt < 2; mt++) {
                const int row = wm * 32 + mt * 16 + r;
                const char* a0 = sAh + row * ROWB + kb;
                const char* a1 = sAh + (row + 8) * ROWB + kb;
                ah[mt][0] = *(const uint32_t*)(a0);
                ah[mt][1] = *(const uint32_t*)(a1);
                ah[mt][2] = *(const uint32_t*)(a0 + 16);
                ah[mt][3] = *(const uint32_t*)(a1 + 16);
                if (NT == 3) {
                    const char* b0 = sAl + row * ROWB + kb;
                    const char* b1 = sAl + (row + 8) * ROWB + kb;
                    al[mt][0] = *(const uint32_t*)(b0);
                    al[mt][1] = *(const uint32_t*)(b1);
                    al[mt][2] = *(const uint32_t*)(b0 + 16);
                    al[mt][3] = *(const uint32_t*)(b1 + 16);
                }
            }
#pragma unroll
            for (int nt = 0; nt < 8; nt++) {
                const int n = wn * 64 + nt * 8 + r;
                uint32_t bh[2];
                const char* p = sBh + n * ROWB + kb;
                bh[0] = *(const uint32_t*)(p);
                bh[1] = *(const uint32_t*)(p + 16);
#pragma unroll
                for (int mt = 0; mt < 2; mt++) {
                    MMA_F16(acc[mt][nt], ah[mt], bh);
                    if (NT == 3) MMA_F16(acc[mt][nt], al[mt], bh);
                }
                if (NT == 3) {
                    uint32_t bl[2];
                    const char* q = sBl + n * ROWB + kb;
                    bl[0] = *(const uint32_t*)(q);
                    bl[1] = *(const uint32_t*)(q + 16);
#pragma unroll
                    for (int mt = 0; mt < 2; mt++)
                        MMA_F16(acc[mt][nt], ah[mt], bl);
                }
            }
        }

        if (c + 2 < nch) {
            __syncthreads();
            load_stage<NT>(pAh, pAl, pBh, pBl, (c + 2) * KC, K,
                           smem + (c & 1) * STG, tid);
        }
    }

    // epilogue
    const int cq = (lane & 3) * 2;
    if (OUT == 0) {
        float* Cw = C + (size_t)blockIdx.z * sC
                      + (size_t)(m0 + wm * 32) * ldC + n0 + wn * 64;
#pragma unroll
        for (int mt = 0; mt < 2; mt++)
#pragma unroll
            for (int nt = 0; nt < 8; nt++) {
                float* p0 = Cw + (size_t)(mt * 16 + r) * ldC + nt * 8 + cq;
                float* p1 = p0 + 8 * (size_t)ldC;
                *(float2*)p0 = make_float2(acc[mt][nt][0] * oscale, acc[mt][nt][1] * oscale);
                *(float2*)p1 = make_float2(acc[mt][nt][2] * oscale, acc[mt][nt][3] * oscale);
            }
    } else {
        const size_t off = (size_t)blockIdx.z * sC
                         + (size_t)(m0 + wm * 32) * ldC + n0 + wn * 64;
        __half* Hw = Chi + off;
        __half* Lw = (OUT == 1) ? Clo + off : nullptr;
#pragma unroll
        for (int mt = 0; mt < 2; mt++)
#pragma unroll
            for (int nt = 0; nt < 8; nt++) {
                const size_t o0 = (size_t)(mt * 16 + r) * ldC + nt * 8 + cq;
                const size_t o1 = o0 + 8 * (size_t)ldC;
                float x0 = acc[mt][nt][0] * oscale, x1 = acc[mt][nt][1] * oscale;
                float x2 = acc[mt][nt][2] * oscale, x3 = acc[mt][nt][3] * oscale;
                __half h0 = __float2half_rn(x0), h1 = __float2half_rn(x1);
                __half h2 = __float2half_rn(x2), h3 = __float2half_rn(x3);
                *(__half2*)(Hw + o0) = __halves2half2(h0, h1);
                *(__half2*)(Hw + o1) = __halves2half2(h2, h3);
                if (OUT == 1) {
                    __half l0 = __float2half_rn(x0 - __half2float(h0));
                    __half l1 = __float2half_rn(x1 - __half2float(h1));
                    __half l2 = __float2half_rn(x2 - __half2float(h2));
                    __half l3 = __float2half_rn(x3 - __half2float(h3));
                    *(__half2*)(Lw + o0) = __halves2half2(l0, l1);
                    *(__half2*)(Lw + o1) = __halves2half2(l2, l3);
                }
            }
    }
}

// ---------------------------------------------------------------------------
// fp32 -> fp16 hi/lo split (elementwise)
// ---------------------------------------------------------------------------
__global__ __launch_bounds__(256)
void split_plain(const float* __restrict__ in, __half* __restrict__ hi,
                 __half* __restrict__ lo, size_t n)
{
    size_t i = ((size_t)blockIdx.x * 256 + threadIdx.x) * 4;
    if (i >= n) return;
    float4 x = *(const float4*)(in + i);
    __half h0 = __float2half_rn(x.x), h1 = __float2half_rn(x.y);
    __half h2 = __float2half_rn(x.z), h3 = __float2half_rn(x.w);
    __half l0 = __float2half_rn(x.x - __half2float(h0));
    __half l1 = __float2half_rn(x.y - __half2float(h1));
    __half l2 = __float2half_rn(x.z - __half2float(h2));
    __half l3 = __float2half_rn(x.w - __half2float(h3));
    *(__half2*)(hi + i)     = __halves2half2(h0, h1);
    *(__half2*)(hi + i + 2) = __halves2half2(h2, h3);
    *(__half2*)(lo + i)     = __halves2half2(l0, l1);
    *(__half2*)(lo + i + 2) = __halves2half2(l2, l3);
}

// ---------------------------------------------------------------------------
// fp32 [R,C] -> transposed, scaled fp16 hi/lo [C,R]
// ---------------------------------------------------------------------------
__global__ __launch_bounds__(256)
void transpose_split(const float* __restrict__ in, __half* __restrict__ hiT,
                     __half* __restrict__ loT, int R, int C, float scale)
{
    __shared__ float t[32][33];
    const int r0 = blockIdx.y * 32, c0 = blockIdx.x * 32;
    const int tx = threadIdx.x & 31, ty = threadIdx.x >> 5;
#pragma unroll
    for (int i = ty; i < 32; i += 8)
        t[i][tx] = in[(size_t)(r0 + i) * C + c0 + tx];
    __syncthreads();
#pragma unroll
    for (int i = ty; i < 32; i += 8) {
        float x = t[tx][i] * scale;
        __half h = __float2half_rn(x);
        __half l = __float2half_rn(x - __half2float(h));
        size_t o = (size_t)(c0 + i) * R + r0 + tx;
        hiT[o] = h; loT[o] = l;
    }
}

// fp16 [R,C] -> transposed fp16 [C,R] (batched via z)
__global__ __launch_bounds__(256)
void transpose_h2h(const __half* __restrict__ in, __half* __restrict__ outT,
                   int R, int C, long long sIn, long long sOut)
{
    __shared__ __half t[32][33];
    in   += (size_t)blockIdx.z * sIn;
    outT += (size_t)blockIdx.z * sOut;
    const int r0 = blockIdx.y * 32, c0 = blockIdx.x * 32;
    const int tx = threadIdx.x & 31, ty = threadIdx.x >> 5;
#pragma unroll
    for (int i = ty; i < 32; i += 8)
        t[i][tx] = in[(size_t)(r0 + i) * C + c0 + tx];
    __syncthreads();
#pragma unroll
    for (int i = ty; i < 32; i += 8)
        outT[(size_t)(c0 + i) * R + r0 + tx] = t[tx][i];
}

// ---------------------------------------------------------------------------
// Row softmax (4096 cols), write fp16 (hi only)
// ---------------------------------------------------------------------------
__global__ __launch_bounds__(256)
void softmax_f16(const float* __restrict__ S, __half* __restrict__ Ph)
{
    const size_t row = blockIdx.x;
    const float* p = S + row * (size_t)SS;
    const int tid = threadIdx.x;

    float4 v[4];
    float m = -INFINITY;
#pragma unroll
    for (int i = 0; i < 4; i++) {
        v[i] = ((const float4*)p)[tid + i * 256];
        m = fmaxf(m, fmaxf(fmaxf(v[i].x, v[i].y), fmaxf(v[i].z, v[i].w)));
    }
    __shared__ float red[256];
    red[tid] = m; __syncthreads();
#pragma unroll
    for (int s = 128; s > 0; s >>= 1) {
        if (tid < s) red[tid] = fmaxf(red[tid], red[tid + s]);
        __syncthreads();
    }
    const float rowmax = red[0];
    __syncthreads();

    float sum = 0.0f;
#pragma unroll
    for (int i = 0; i < 4; i++) {
        v[i].x = __expf(v[i].x - rowmax);
        v[i].y = __expf(v[i].y - rowmax);
        v[i].z = __expf(v[i].z - rowmax);
        v[i].w = __expf(v[i].w - rowmax);
        sum += v[i].x + v[i].y + v[i].z + v[i].w;
    }
    red[tid] = sum; __syncthreads();
#pragma unroll
    for (int s = 128; s > 0; s >>= 1) {
        if (tid < s) red[tid] += red[tid + s];
        __syncthreads();
    }
    const float inv = 1.0f / red[0];
    __syncthreads();

#pragma unroll
    for (int i = 0; i < 4; i++) {
        size_t o = row * (size_t)SS + (size_t)(tid + i * 256) * 4;
        *(__half2*)(Ph + o)     = __halves2half2(__float2half_rn(v[i].x * inv),
                                                 __float2half_rn(v[i].y * inv));
        *(__half2*)(Ph + o + 2) = __halves2half2(__float2half_rn(v[i].z * inv),
                                                 __float2half_rn(v[i].w * inv));
    }
}

// ---------------------------------------------------------------------------
// kernel_launch — graph-capturable pipeline
// ---------------------------------------------------------------------------
extern "C" void kernel_launch(void* const* d_in, const int* in_sizes, int n_in,
                              void* d_out, int out_size)
{
    const float* X  = (const float*)d_in[0];
    const float* Wq = (const float*)d_in[1];
    const float* Wk = (const float*)d_in[2];
    const float* Wv = (const float*)d_in[3];
    float* out = (float*)d_out;

    float *Sc;
    __half *Vh, *Xhi, *Xlo, *Wh, *Wl, *Qhi, *Qlo, *Khi, *Klo, *Vthi, *Phi;
    cudaGetSymbolAddress((void**)&Sc, g_S);
    cudaGetSymbolAddress((void**)&Vh, g_Vh);
    cudaGetSymbolAddress((void**)&Xhi, g_Xhi);
    cudaGetSymbolAddress((void**)&Xlo, g_Xlo);
    cudaGetSymbolAddress((void**)&Wh, g_Wh);
    cudaGetSymbolAddress((void**)&Wl, g_Wl);
    cudaGetSymbolAddress((void**)&Qhi, g_Qhi);
    cudaGetSymbolAddress((void**)&Qlo, g_Qlo);
    cudaGetSymbolAddress((void**)&Khi, g_Khi);
    cudaGetSymbolAddress((void**)&Klo, g_Klo);
    cudaGetSymbolAddress((void**)&Vthi, g_Vthi);
    cudaGetSymbolAddress((void**)&Phi, g_Phi);

    const int SMEM_NT3 = 2 * 4 * TILE_T;   // 81920
    const int SMEM_NT1 = 2 * 2 * TILE_T;   // 40960
    cudaFuncSetAttribute(gemm_mma<3,0>, cudaFuncAttributeMaxDynamicSharedMemorySize, SMEM_NT3);
    cudaFuncSetAttribute(gemm_mma<3,1>, cudaFuncAttributeMaxDynamicSharedMemorySize, SMEM_NT3);
    cudaFuncSetAttribute(gemm_mma<1,0>, cudaFuncAttributeMaxDynamicSharedMemorySize, SMEM_NT1);
    cudaFuncSetAttribute(gemm_mma<1,2>, cudaFuncAttributeMaxDynamicSharedMemorySize, SMEM_NT1);

    const size_t WSZ = (size_t)AA * DD;
    const float WS = 16.0f, INV_WS = 1.0f / 16.0f;

    // 1) split X; transpose+split the three weight matrices (scaled by 16)
    split_plain<<<(MTOT * (size_t)DD) / 1024, 256>>>(X, Xhi, Xlo, (size_t)MTOT * DD);
    {
        dim3 g(AA / 32, DD / 32, 1);
        transpose_split<<<g, 256>>>(Wq, Wh + 0 * WSZ, Wl + 0 * WSZ, DD, AA, WS);
        transpose_split<<<g, 256>>>(Wk, Wh + 1 * WSZ, Wl + 1 * WSZ, DD, AA, WS);
        transpose_split<<<g, 256>>>(Wv, Wh + 2 * WSZ, Wl + 2 * WSZ, DD, AA, WS);
    }

    // 2) projections: Q,K 3-term -> fp16 hi/lo; V 1-term -> fp16 direct
    {
        dim3 g(AA / 128, MTOT / 128, 1);
        gemm_mma<3,1><<<g, 256, SMEM_NT3>>>(Xhi, Xlo, Wh + 0*WSZ, Wl + 0*WSZ,
                                            nullptr, Qhi, Qlo, DD, AA, 0, 0, 0, INV_WS);
        gemm_mma<3,1><<<g, 256, SMEM_NT3>>>(Xhi, Xlo, Wh + 1*WSZ, Wl + 1*WSZ,
                                            nullptr, Khi, Klo, DD, AA, 0, 0, 0, INV_WS);
        gemm_mma<1,2><<<g, 256, SMEM_NT1>>>(Xhi, nullptr, Wh + 2*WSZ, nullptr,
                                            nullptr, Vh, nullptr, DD, AA, 0, 0, 0, INV_WS);
    }

    // 3) transpose V per batch to fp16 [A,S]
    {
        dim3 g(AA / 32, SS / 32, BB);
        transpose_h2h<<<g, 256>>>(Vh, Vthi, SS, AA,
                                  (long long)SS * AA, (long long)SS * AA);
    }

    // 4) scores (3-term): S = Q @ K^T per batch
    {
        dim3 g(SS / 128, SS / 128, BB);
        gemm_mma<3,0><<<g, 256, SMEM_NT3>>>(Qhi, Qlo, Khi, Klo, Sc, nullptr, nullptr,
                                            AA, SS,
                                            (long long)SS * AA, (long long)SS * AA,
                                            (long long)SS * SS, 1.0f);
    }

    // 5) softmax -> fp16 P (hi only)
    softmax_f16<<<BB * SS, 256>>>(Sc, Phi);

    // 6) output (1-term): O = P @ V per batch
    {
        dim3 g(AA / 128, SS / 128, BB);
        gemm_mma<1,0><<<g, 256, SMEM_NT1>>>(Phi, nullptr, Vthi, nullptr,
                                            out, nullptr, nullptr,
                                            SS, AA,
                                            (long long)SS * SS, (long long)AA * SS,
                                            (long long)SS * AA, 1.0f);
    }
}

// round 12
// speedup vs baseline: 1.8924x; 1.1111x over previous
#include <cuda_runtime.h>
#include <cuda_fp16.h>
#include <cstdint>
#include <math.h>

// Problem dims (fixed)
#define BB 4
#define SS 4096
#define DD 1024
#define AA 1024
#define MTOT (BB*SS)   // 16384

// ---------------------------------------------------------------------------
// Device scratch
// ---------------------------------------------------------------------------
__device__ float g_S [(size_t)BB * SS * SS];              // 256 MB scores
__device__ __half g_Vh[(size_t)MTOT * AA];                // V projection, fp16
__device__ __half g_Xhi[(size_t)MTOT * DD];
__device__ __half g_Xlo[(size_t)MTOT * DD];
__device__ __half g_Wq16h[(size_t)DD * AA];               // 16*Wq split (row-major [D,A])
__device__ __half g_Wq16l[(size_t)DD * AA];
__device__ __half g_Wk16h[(size_t)DD * AA];
__device__ __half g_Wk16l[(size_t)DD * AA];
__device__ __half g_WvTh[(size_t)AA * DD];                // (16*Wv)^T hi [A,D]
__device__ __half g_Wth[(size_t)DD * DD];                 // 16*W~^T hi/lo [d2,d1]
__device__ __half g_Wtl[(size_t)DD * DD];
__device__ __half g_Yhi[(size_t)MTOT * DD];               // Y = X*W~ split
__device__ __half g_Ylo[(size_t)MTOT * DD];
__device__ __half g_Vthi[(size_t)BB * AA * SS];           // V^T per batch [A,S]
__device__ __half g_Phi[(size_t)BB * SS * SS];            // 128 MB

// ---------------------------------------------------------------------------
// Helpers
// ---------------------------------------------------------------------------
__device__ __forceinline__ uint32_t smem_u32(const void* p) {
    uint32_t a;
    asm("{ .reg .u64 t; cvta.to.shared.u64 t, %1; cvt.u32.u64 %0, t; }" : "=r"(a) : "l"(p));
    return a;
}

#define CP_ASYNC16(saddr, gaddr) \
    asm volatile("cp.async.cg.shared.global [%0], [%1], 16;" :: "r"(saddr), "l"(gaddr))
#define CP_COMMIT()  asm volatile("cp.async.commit_group;" ::: "memory")
#define CP_WAIT1()   asm volatile("cp.async.wait_group 1;" ::: "memory")
#define CP_WAIT0()   asm volatile("cp.async.wait_group 0;" ::: "memory")

#define MMA_F16(c, a, b) \
    asm volatile("mma.sync.aligned.m16n8k16.row.col.f32.f16.f16.f32 " \
        "{%0,%1,%2,%3}, {%4,%5,%6,%7}, {%8,%9}, {%0,%1,%2,%3};" \
        : "+f"((c)[0]), "+f"((c)[1]), "+f"((c)[2]), "+f"((c)[3]) \
        : "r"((a)[0]), "r"((a)[1]), "r"((a)[2]), "r"((a)[3]), \
          "r"((b)[0]), "r"((b)[1]))

// ---------------------------------------------------------------------------
// HMMA GEMM, fp16 hi/lo split, term count NT (all f32-accumulate):
//   NT=3: AhBh + AlBh + AhBl ; NT=1: AhBh
// OUT: 0 = fp32 C; 1 = fp16 hi/lo pair (Chi,Clo); 2 = fp16 hi only (Chi)
// C[M,N] = A[M,K] * B[N,K]^T, K-major. CTA tile 128x128, KC=32,
// 2-stage cp.async double buffer, 2 CTAs/SM, warp tile 32x64.
// ---------------------------------------------------------------------------
#define KC    32
#define ROWB  80                              // 32 fp16 (64B) + 16B pad
#define TILE_T (128 * ROWB)                   // 10240 B

__device__ __forceinline__ void load_tile32(const __half* __restrict__ g,
                                            int ldK, char* sb, int tid)
{
#pragma unroll
    for (int i = 0; i < 2; i++) {
        int ch = tid + i * 256;               // 0..511
        int row = ch >> 2, c = ch & 3;
        CP_ASYNC16(smem_u32(sb + row * ROWB + c * 16),
                   g + (size_t)row * ldK + c * 8);
    }
}

template <int NT>
__device__ __forceinline__ void load_stage(const __half* pAh, const __half* pAl,
                                           const __half* pBh, const __half* pBl,
                                           int k0, int K, char* sp, int tid)
{
    load_tile32(pAh + k0, K, sp, tid);
    if (NT == 3) {
        load_tile32(pAl + k0, K, sp + TILE_T,     tid);
        load_tile32(pBh + k0, K, sp + 2 * TILE_T, tid);
        load_tile32(pBl + k0, K, sp + 3 * TILE_T, tid);
    } else {
        load_tile32(pBh + k0, K, sp + TILE_T, tid);
    }
    CP_COMMIT();
}

template <int NT, int OUT>
__global__ __launch_bounds__(256, 2)
void gemm_mma(const __half* __restrict__ Ahi, const __half* __restrict__ Alo,
              const __half* __restrict__ Bhi, const __half* __restrict__ Blo,
              float* __restrict__ C,
              __half* __restrict__ Chi, __half* __restrict__ Clo,
              int K, int ldC,
              long long sA, long long sB, long long sC, float oscale)
{
    constexpr int STG = (NT == 3 ? 4 : 2) * TILE_T;
    extern __shared__ __align__(128) char smem[];
    const int tid = threadIdx.x;
    const int wid = tid >> 5, lane = tid & 31;
    const int wm = wid & 3, wn = wid >> 2;    // 4(m) x 2(n)
    const int m0 = blockIdx.y * 128;
    const int n0 = blockIdx.x * 128;

    const __half* pAh = Ahi + (size_t)blockIdx.z * sA + (size_t)m0 * K;
    const __half* pAl = (NT == 3) ? Alo + (size_t)blockIdx.z * sA + (size_t)m0 * K : nullptr;
    const __half* pBh = Bhi + (size_t)blockIdx.z * sB + (size_t)n0 * K;
    const __half* pBl = (NT == 3) ? Blo + (size_t)blockIdx.z * sB + (size_t)n0 * K : nullptr;

    float acc[2][8][4];
#pragma unroll
    for (int mt = 0; mt < 2; mt++)
#pragma unroll
        for (int nt = 0; nt < 8; nt++)
#pragma unroll
            for (int j = 0; j < 4; j++) acc[mt][nt][j] = 0.0f;

    const int nch = K >> 5;

    load_stage<NT>(pAh, pAl, pBh, pBl, 0,  K, smem,       tid);
    load_stage<NT>(pAh, pAl, pBh, pBl, KC, K, smem + STG, tid);

    const int r  = lane >> 2;        // 0..7
    const int kq = lane & 3;         // 0..3

    for (int c = 0; c < nch; ++c) {
        if (c + 1 < nch) CP_WAIT1(); else CP_WAIT0();
        __syncthreads();

        const char* sp  = smem + (c & 1) * STG;
        const char* sAh = sp;
        const char* sAl = sp + TILE_T;                       // NT==3
        const char* sBh = sp + (NT == 3 ? 2 : 1) * TILE_T;
        const char* sBl = sp + 3 * TILE_T;                   // NT==3

#pragma unroll
        for (int ks = 0; ks < 2; ++ks) {
            const int kb = ks * 32 + kq * 4;

            uint32_t ah[2][4], al[2][4];
#pragma unroll
            for (int mt = 0; mt < 2; mt++) {
                const int row = wm * 32 + mt * 16 + r;
                const char* a0 = sAh + row * ROWB + kb;
                const char* a1 = sAh + (row + 8) * ROWB + kb;
                ah[mt][0] = *(const uint32_t*)(a0);
                ah[mt][1] = *(const uint32_t*)(a1);
                ah[mt][2] = *(const uint32_t*)(a0 + 16);
                ah[mt][3] = *(const uint32_t*)(a1 + 16);
                if (NT == 3) {
                    const char* b0 = sAl + row * ROWB + kb;
                    const char* b1 = sAl + (row + 8) * ROWB + kb;
                    al[mt][0] = *(const uint32_t*)(b0);
                    al[mt][1] = *(const uint32_t*)(b1);
                    al[mt][2] = *(const uint32_t*)(b0 + 16);
                    al[mt][3] = *(const uint32_t*)(b1 + 16);
                }
            }
#pragma unroll
            for (int nt = 0; nt < 8; nt++) {
                const int n = wn * 64 + nt * 8 + r;
                uint32_t bh[2];
                const char* p = sBh + n * ROWB + kb;
                bh[0] = *(const uint32_t*)(p);
                bh[1] = *(const uint32_t*)(p + 16);
#pragma unroll
                for (int mt = 0; mt < 2; mt++) {
                    MMA_F16(acc[mt][nt], ah[mt], bh);
                    if (NT == 3) MMA_F16(acc[mt][nt], al[mt], bh);
                }
                if (NT == 3) {
                    uint32_t bl[2];
                    const char* q = sBl + n * ROWB + kb;
                    bl[0] = *(const uint32_t*)(q);
                    bl[1] = *(const uint32_t*)(q + 16);
#pragma unroll
                    for (int mt = 0; mt < 2; mt++)
                        MMA_F16(acc[mt][nt], ah[mt], bl);
                }
            }
        }

        if (c + 2 < nch) {
            __syncthreads();
            load_stage<NT>(pAh, pAl, pBh, pBl, (c + 2) * KC, K,
                           smem + (c & 1) * STG, tid);
        }
    }

    // epilogue
    const int cq = (lane & 3) * 2;
    if (OUT == 0) {
        float* Cw = C + (size_t)blockIdx.z * sC
                      + (size_t)(m0 + wm * 32) * ldC + n0 + wn * 64;
#pragma unroll
        for (int mt = 0; mt < 2; mt++)
#pragma unroll
            for (int nt = 0; nt < 8; nt++) {
                float* p0 = Cw + (size_t)(mt * 16 + r) * ldC + nt * 8 + cq;
                float* p1 = p0 + 8 * (size_t)ldC;
                *(float2*)p0 = make_float2(acc[mt][nt][0] * oscale, acc[mt][nt][1] * oscale);
                *(float2*)p1 = make_float2(acc[mt][nt][2] * oscale, acc[mt][nt][3] * oscale);
            }
    } else {
        const size_t off = (size_t)blockIdx.z * sC
                         + (size_t)(m0 + wm * 32) * ldC + n0 + wn * 64;
        __half* Hw = Chi + off;
        __half* Lw = (OUT == 1) ? Clo + off : nullptr;
#pragma unroll
        for (int mt = 0; mt < 2; mt++)
#pragma unroll
            for (int nt = 0; nt < 8; nt++) {
                const size_t o0 = (size_t)(mt * 16 + r) * ldC + nt * 8 + cq;
                const size_t o1 = o0 + 8 * (size_t)ldC;
                float x0 = acc[mt][nt][0] * oscale, x1 = acc[mt][nt][1] * oscale;
                float x2 = acc[mt][nt][2] * oscale, x3 = acc[mt][nt][3] * oscale;
                __half h0 = __float2half_rn(x0), h1 = __float2half_rn(x1);
                __half h2 = __float2half_rn(x2), h3 = __float2half_rn(x3);
                *(__half2*)(Hw + o0) = __halves2half2(h0, h1);
                *(__half2*)(Hw + o1) = __halves2half2(h2, h3);
                if (OUT == 1) {
                    __half l0 = __float2half_rn(x0 - __half2float(h0));
                    __half l1 = __float2half_rn(x1 - __half2float(h1));
                    __half l2 = __float2half_rn(x2 - __half2float(h2));
                    __half l3 = __float2half_rn(x3 - __half2float(h3));
                    *(__half2*)(Lw + o0) = __halves2half2(l0, l1);
                    *(__half2*)(Lw + o1) = __halves2half2(l2, l3);
                }
            }
    }
}

// ---------------------------------------------------------------------------
// fp32 -> scaled fp16 hi/lo split (elementwise)
// ---------------------------------------------------------------------------
__global__ __launch_bounds__(256)
void split_plain(const float* __restrict__ in, __half* __restrict__ hi,
                 __half* __restrict__ lo, size_t n, float scale)
{
    size_t i = ((size_t)blockIdx.x * 256 + threadIdx.x) * 4;
    if (i >= n) return;
    float4 x = *(const float4*)(in + i);
    x.x *= scale; x.y *= scale; x.z *= scale; x.w *= scale;
    __half h0 = __float2half_rn(x.x), h1 = __float2half_rn(x.y);
    __half h2 = __float2half_rn(x.z), h3 = __float2half_rn(x.w);
    __half l0 = __float2half_rn(x.x - __half2float(h0));
    __half l1 = __float2half_rn(x.y - __half2float(h1));
    __half l2 = __float2half_rn(x.z - __half2float(h2));
    __half l3 = __float2half_rn(x.w - __half2float(h3));
    *(__half2*)(hi + i)     = __halves2half2(h0, h1);
    *(__half2*)(hi + i + 2) = __halves2half2(h2, h3);
    *(__half2*)(lo + i)     = __halves2half2(l0, l1);
    *(__half2*)(lo + i + 2) = __halves2half2(l2, l3);
}

// fp32 [R,C] -> transposed, scaled fp16 hi only [C,R]
__global__ __launch_bounds__(256)
void transpose_hi16(const float* __restrict__ in, __half* __restrict__ hiT,
                    int R, int C, float scale)
{
    __shared__ float t[32][33];
    const int r0 = blockIdx.y * 32, c0 = blockIdx.x * 32;
    const int tx = threadIdx.x & 31, ty = threadIdx.x >> 5;
#pragma unroll
    for (int i = ty; i < 32; i += 8)
        t[i][tx] = in[(size_t)(r0 + i) * C + c0 + tx];
    __syncthreads();
#pragma unroll
    for (int i = ty; i < 32; i += 8)
        hiT[(size_t)(c0 + i) * R + r0 + tx] = __float2half_rn(t[tx][i] * scale);
}

// fp16 [R,C] -> transposed fp16 [C,R] (batched via z)
__global__ __launch_bounds__(256)
void transpose_h2h(const __half* __restrict__ in, __half* __restrict__ outT,
                   int R, int C, long long sIn, long long sOut)
{
    __shared__ __half t[32][33];
    in   += (size_t)blockIdx.z * sIn;
    outT += (size_t)blockIdx.z * sOut;
    const int r0 = blockIdx.y * 32, c0 = blockIdx.x * 32;
    const int tx = threadIdx.x & 31, ty = threadIdx.x >> 5;
#pragma unroll
    for (int i = ty; i < 32; i += 8)
        t[i][tx] = in[(size_t)(r0 + i) * C + c0 + tx];
    __syncthreads();
#pragma unroll
    for (int i = ty; i < 32; i += 8)
        outT[(size_t)(c0 + i) * R + r0 + tx] = t[tx][i];
}

// ---------------------------------------------------------------------------
// Row softmax (4096 cols), write fp16 (hi only)
// ---------------------------------------------------------------------------
__global__ __launch_bounds__(256)
void softmax_f16(const float* __restrict__ S, __half* __restrict__ Ph)
{
    const size_t row = blockIdx.x;
    const float* p = S + row * (size_t)SS;
    const int tid = threadIdx.x;

    float4 v[4];
    float m = -INFINITY;
#pragma unroll
    for (int i = 0; i < 4; i++) {
        v[i] = ((const float4*)p)[tid + i * 256];
        m = fmaxf(m, fmaxf(fmaxf(v[i].x, v[i].y), fmaxf(v[i].z, v[i].w)));
    }
    __shared__ float red[256];
    red[tid] = m; __syncthreads();
#pragma unroll
    for (int s = 128; s > 0; s >>= 1) {
        if (tid < s) red[tid] = fmaxf(red[tid], red[tid + s]);
        __syncthreads();
    }
    const float rowmax = red[0];
    __syncthreads();

    float sum = 0.0f;
#pragma unroll
    for (int i = 0; i < 4; i++) {
        v[i].x = __expf(v[i].x - rowmax);
        v[i].y = __expf(v[i].y - rowmax);
        v[i].z = __expf(v[i].z - rowmax);
        v[i].w = __expf(v[i].w - rowmax);
        sum += v[i].x + v[i].y + v[i].z + v[i].w;
    }
    red[tid] = sum; __syncthreads();
#pragma unroll
    for (int s = 128; s > 0; s >>= 1) {
        if (tid < s) red[tid] += red[tid + s];
        __syncthreads();
    }
    const float inv = 1.0f / red[0];
    __syncthreads();

#pragma unroll
    for (int i = 0; i < 4; i++) {
        size_t o = row * (size_t)SS + (size_t)(tid + i * 256) * 4;
        *(__half2*)(Ph + o)     = __halves2half2(__float2half_rn(v[i].x * inv),
                                                 __float2half_rn(v[i].y * inv));
        *(__half2*)(Ph + o + 2) = __halves2half2(__float2half_rn(v[i].z * inv),
                                                 __float2half_rn(v[i].w * inv));
    }
}

// ---------------------------------------------------------------------------
// kernel_launch — graph-capturable pipeline
//   S = X (Wq Wk^T) X^T  via  Wt = Wk Wq^T,  Y = X Wt^T(row form),  S = Y X^T
// ---------------------------------------------------------------------------
extern "C" void kernel_launch(void* const* d_in, const int* in_sizes, int n_in,
                              void* d_out, int out_size)
{
    const float* X  = (const float*)d_in[0];
    const float* Wq = (const float*)d_in[1];
    const float* Wk = (const float*)d_in[2];
    const float* Wv = (const float*)d_in[3];
    float* out = (float*)d_out;

    float *Sc;
    __half *Vh, *Xhi, *Xlo, *Wq16h, *Wq16l, *Wk16h, *Wk16l, *WvTh;
    __half *Wth, *Wtl, *Yhi, *Ylo, *Vthi, *Phi;
    cudaGetSymbolAddress((void**)&Sc, g_S);
    cudaGetSymbolAddress((void**)&Vh, g_Vh);
    cudaGetSymbolAddress((void**)&Xhi, g_Xhi);
    cudaGetSymbolAddress((void**)&Xlo, g_Xlo);
    cudaGetSymbolAddress((void**)&Wq16h, g_Wq16h);
    cudaGetSymbolAddress((void**)&Wq16l, g_Wq16l);
    cudaGetSymbolAddress((void**)&Wk16h, g_Wk16h);
    cudaGetSymbolAddress((void**)&Wk16l, g_Wk16l);
    cudaGetSymbolAddress((void**)&WvTh, g_WvTh);
    cudaGetSymbolAddress((void**)&Wth, g_Wth);
    cudaGetSymbolAddress((void**)&Wtl, g_Wtl);
    cudaGetSymbolAddress((void**)&Yhi, g_Yhi);
    cudaGetSymbolAddress((void**)&Ylo, g_Ylo);
    cudaGetSymbolAddress((void**)&Vthi, g_Vthi);
    cudaGetSymbolAddress((void**)&Phi, g_Phi);

    const int SMEM_NT3 = 2 * 4 * TILE_T;   // 81920
    const int SMEM_NT1 = 2 * 2 * TILE_T;   // 40960
    cudaFuncSetAttribute(gemm_mma<3,0>, cudaFuncAttributeMaxDynamicSharedMemorySize, SMEM_NT3);
    cudaFuncSetAttribute(gemm_mma<3,1>, cudaFuncAttributeMaxDynamicSharedMemorySize, SMEM_NT3);
    cudaFuncSetAttribute(gemm_mma<1,0>, cudaFuncAttributeMaxDynamicSharedMemorySize, SMEM_NT1);
    cudaFuncSetAttribute(gemm_mma<1,2>, cudaFuncAttributeMaxDynamicSharedMemorySize, SMEM_NT1);

    const float INV16 = 1.0f / 16.0f;

    // 1) splits: X (unscaled), Wq/Wk (x16, no transpose), Wv^T hi (x16)
    split_plain<<<(MTOT * (size_t)DD) / 1024, 256>>>(X, Xhi, Xlo, (size_t)MTOT * DD, 1.0f);
    split_plain<<<((size_t)DD * AA) / 1024, 256>>>(Wq, Wq16h, Wq16l, (size_t)DD * AA, 16.0f);
    split_plain<<<((size_t)DD * AA) / 1024, 256>>>(Wk, Wk16h, Wk16l, (size_t)DD * AA, 16.0f);
    {
        dim3 g(AA / 32, DD / 32, 1);
        transpose_hi16<<<g, 256>>>(Wv, WvTh, DD, AA, 16.0f);
    }

    // 2) Wt = Wk Wq^T (3-term): inputs x16 each -> raw 256*Wt; store 16*Wt hi/lo
    {
        dim3 g(DD / 128, DD / 128, 1);
        gemm_mma<3,1><<<g, 256, SMEM_NT3>>>(Wk16h, Wk16l, Wq16h, Wq16l,
                                            nullptr, Wth, Wtl, AA, DD, 0, 0, 0, INV16);
    }

    // 3) V projection (1-term): Vh = fp16(X @ Wv)
    {
        dim3 g(AA / 128, MTOT / 128, 1);
        gemm_mma<1,2><<<g, 256, SMEM_NT1>>>(Xhi, nullptr, WvTh, nullptr,
                                            nullptr, Vh, nullptr, DD, AA, 0, 0, 0, INV16);
    }

    // 4) Y = X @ Wt^T-row-form (3-term): raw 16*Y; store Y hi/lo
    {
        dim3 g(DD / 128, MTOT / 128, 1);
        gemm_mma<3,1><<<g, 256, SMEM_NT3>>>(Xhi, Xlo, Wth, Wtl,
                                            nullptr, Yhi, Ylo, DD, DD, 0, 0, 0, INV16);
    }

    // 5) transpose V per batch to fp16 [A,S]
    {
        dim3 g(AA / 32, SS / 32, BB);
        transpose_h2h<<<g, 256>>>(Vh, Vthi, SS, AA,
                                  (long long)SS * AA, (long long)SS * AA);
    }

    // 6) scores (3-term): S = Y @ X^T per batch
    {
        dim3 g(SS / 128, SS / 128, BB);
        gemm_mma<3,0><<<g, 256, SMEM_NT3>>>(Yhi, Ylo, Xhi, Xlo, Sc, nullptr, nullptr,
                                            DD, SS,
                                            (long long)SS * DD, (long long)SS * DD,
                                            (long long)SS * SS, 1.0f);
    }

    // 7) softmax -> fp16 P (hi only)
    softmax_f16<<<BB * SS, 256>>>(Sc, Phi);

    // 8) output (1-term): O = P @ V per batch
    {
        dim3 g(AA / 128, SS / 128, BB);
        gemm_mma<1,0><<<g, 256, SMEM_NT1>>>(Phi, nullptr, Vthi, nullptr,
                                            out, nullptr, nullptr,
                                            SS, AA,
                                            (long long)SS * SS, (long long)AA * SS,
                                            (long long)SS * AA, 1.0f);
    }
}

// round 13
// speedup vs baseline: 1.9251x; 1.0173x over previous
#include <cuda_runtime.h>
#include <cuda_fp16.h>
#include <cstdint>
#include <math.h>

// Problem dims (fixed)
#define BB 4
#define SS 4096
#define DD 1024
#define AA 1024
#define MTOT (BB*SS)   // 16384

// ---------------------------------------------------------------------------
// Device scratch
// ---------------------------------------------------------------------------
__device__ float g_S [(size_t)BB * SS * SS];              // 256 MB scores
__device__ float g_Wt_part[4 * (size_t)DD * DD];          // 16 MB split-K partials
__device__ __half g_Xhi[(size_t)MTOT * DD];
__device__ __half g_Xlo[(size_t)MTOT * DD];
__device__ __half g_Wq16h[(size_t)DD * AA];               // 16*Wq split (row-major [D,A])
__device__ __half g_Wq16l[(size_t)DD * AA];
__device__ __half g_Wk16h[(size_t)DD * AA];
__device__ __half g_Wk16l[(size_t)DD * AA];
__device__ __half g_WvTh[(size_t)AA * DD];                // (16*Wv)^T hi [A,D]
__device__ __half g_Wth[(size_t)DD * DD];                 // 16*W~^T hi/lo [d2,d1]
__device__ __half g_Wtl[(size_t)DD * DD];
__device__ __half g_Yhi[(size_t)MTOT * DD];               // Y = X*W~ split
__device__ __half g_Ylo[(size_t)MTOT * DD];
__device__ __half g_Vthi[(size_t)BB * AA * SS];           // V^T per batch [A,S]
__device__ __half g_Phi[(size_t)BB * SS * SS];            // 128 MB

// ---------------------------------------------------------------------------
// Helpers
// ---------------------------------------------------------------------------
__device__ __forceinline__ uint32_t smem_u32(const void* p) {
    uint32_t a;
    asm("{ .reg .u64 t; cvta.to.shared.u64 t, %1; cvt.u32.u64 %0, t; }" : "=r"(a) : "l"(p));
    return a;
}

#define CP_ASYNC16(saddr, gaddr) \
    asm volatile("cp.async.cg.shared.global [%0], [%1], 16;" :: "r"(saddr), "l"(gaddr))
#define CP_COMMIT()  asm volatile("cp.async.commit_group;" ::: "memory")
#define CP_WAIT1()   asm volatile("cp.async.wait_group 1;" ::: "memory")
#define CP_WAIT0()   asm volatile("cp.async.wait_group 0;" ::: "memory")

#define MMA_F16(c, a, b) \
    asm volatile("mma.sync.aligned.m16n8k16.row.col.f32.f16.f16.f32 " \
        "{%0,%1,%2,%3}, {%4,%5,%6,%7}, {%8,%9}, {%0,%1,%2,%3};" \
        : "+f"((c)[0]), "+f"((c)[1]), "+f"((c)[2]), "+f"((c)[3]) \
        : "r"((a)[0]), "r"((a)[1]), "r"((a)[2]), "r"((a)[3]), \
          "r"((b)[0]), "r"((b)[1]))

// ---------------------------------------------------------------------------
// HMMA GEMM, fp16 hi/lo split, term count NT (all f32-accumulate):
//   NT=3: AhBh + AlBh + AhBl ; NT=1: AhBh
// OUT: 0 = fp32 C (strided by sC per z); 1 = fp16 hi/lo (Chi,Clo);
//      2 = fp16 hi only; 3 = fp16 hi transposed per 4096-row batch (V^T)
// C[M,N] = A[M,K] * B[N,K]^T. ldAB = row stride of A/B (elements);
// K = reduction length consumed (k-slice via sA/sB element offsets).
// CTA tile 128x128, KC=32, 2-stage cp.async, 2 CTAs/SM, warp tile 32x64.
// ---------------------------------------------------------------------------
#define KC    32
#define ROWB  80                              // 32 fp16 (64B) + 16B pad
#define TILE_T (128 * ROWB)                   // 10240 B

__device__ __forceinline__ void load_tile32(const __half* __restrict__ g,
                                            int ldK, char* sb, int tid)
{
#pragma unroll
    for (int i = 0; i < 2; i++) {
        int ch = tid + i * 256;               // 0..511
        int row = ch >> 2, c = ch & 3;
        CP_ASYNC16(smem_u32(sb + row * ROWB + c * 16),
                   g + (size_t)row * ldK + c * 8);
    }
}

template <int NT>
__device__ __forceinline__ void load_stage(const __half* pAh, const __half* pAl,
                                           const __half* pBh, const __half* pBl,
                                           int k0, int ldAB, char* sp, int tid)
{
    load_tile32(pAh + k0, ldAB, sp, tid);
    if (NT == 3) {
        load_tile32(pAl + k0, ldAB, sp + TILE_T,     tid);
        load_tile32(pBh + k0, ldAB, sp + 2 * TILE_T, tid);
        load_tile32(pBl + k0, ldAB, sp + 3 * TILE_T, tid);
    } else {
        load_tile32(pBh + k0, ldAB, sp + TILE_T, tid);
    }
    CP_COMMIT();
}

template <int NT, int OUT>
__global__ __launch_bounds__(256, 2)
void gemm_mma(const __half* __restrict__ Ahi, const __half* __restrict__ Alo,
              const __half* __restrict__ Bhi, const __half* __restrict__ Blo,
              float* __restrict__ C,
              __half* __restrict__ Chi, __half* __restrict__ Clo,
              int K, int ldAB, int ldC,
              long long sA, long long sB, long long sC, float oscale)
{
    constexpr int STG = (NT == 3 ? 4 : 2) * TILE_T;
    extern __shared__ __align__(128) char smem[];
    const int tid = threadIdx.x;
    const int wid = tid >> 5, lane = tid & 31;
    const int wm = wid & 3, wn = wid >> 2;    // 4(m) x 2(n)
    const int m0 = blockIdx.y * 128;
    const int n0 = blockIdx.x * 128;

    const __half* pAh = Ahi + (size_t)blockIdx.z * sA + (size_t)m0 * ldAB;
    const __half* pAl = (NT == 3) ? Alo + (size_t)blockIdx.z * sA + (size_t)m0 * ldAB : nullptr;
    const __half* pBh = Bhi + (size_t)blockIdx.z * sB + (size_t)n0 * ldAB;
    const __half* pBl = (NT == 3) ? Blo + (size_t)blockIdx.z * sB + (size_t)n0 * ldAB : nullptr;

    float acc[2][8][4];
#pragma unroll
    for (int mt = 0; mt < 2; mt++)
#pragma unroll
        for (int nt = 0; nt < 8; nt++)
#pragma unroll
            for (int j = 0; j < 4; j++) acc[mt][nt][j] = 0.0f;

    const int nch = K >> 5;

    load_stage<NT>(pAh, pAl, pBh, pBl, 0,  ldAB, smem,       tid);
    load_stage<NT>(pAh, pAl, pBh, pBl, KC, ldAB, smem + STG, tid);

    const int r  = lane >> 2;        // 0..7
    const int kq = lane & 3;         // 0..3

    for (int c = 0; c < nch; ++c) {
        if (c + 1 < nch) CP_WAIT1(); else CP_WAIT0();
        __syncthreads();

        const char* sp  = smem + (c & 1) * STG;
        const char* sAh = sp;
        const char* sAl = sp + TILE_T;                       // NT==3
        const char* sBh = sp + (NT == 3 ? 2 : 1) * TILE_T;
        const char* sBl = sp + 3 * TILE_T;                   // NT==3

#pragma unroll
        for (int ks = 0; ks < 2; ++ks) {
            const int kb = ks * 32 + kq * 4;

            uint32_t ah[2][4], al[2][4];
#pragma unroll
            for (int mt = 0; mt < 2; mt++) {
                const int row = wm * 32 + mt * 16 + r;
                const char* a0 = sAh + row * ROWB + kb;
                const char* a1 = sAh + (row + 8) * ROWB + kb;
                ah[mt][0] = *(const uint32_t*)(a0);
                ah[mt][1] = *(const uint32_t*)(a1);
                ah[mt][2] = *(const uint32_t*)(a0 + 16);
                ah[mt][3] = *(const uint32_t*)(a1 + 16);
                if (NT == 3) {
                    const char* b0 = sAl + row * ROWB + kb;
                    const char* b1 = sAl + (row + 8) * ROWB + kb;
                    al[mt][0] = *(const uint32_t*)(b0);
                    al[mt][1] = *(const uint32_t*)(b1);
                    al[mt][2] = *(const uint32_t*)(b0 + 16);
                    al[mt][3] = *(const uint32_t*)(b1 + 16);
                }
            }
#pragma unroll
            for (int nt = 0; nt < 8; nt++) {
                const int n = wn * 64 + nt * 8 + r;
                uint32_t bh[2];
                const char* p = sBh + n * ROWB + kb;
                bh[0] = *(const uint32_t*)(p);
                bh[1] = *(const uint32_t*)(p + 16);
#pragma unroll
                for (int mt = 0; mt < 2; mt++) {
                    MMA_F16(acc[mt][nt], ah[mt], bh);
                    if (NT == 3) MMA_F16(acc[mt][nt], al[mt], bh);
                }
                if (NT == 3) {
                    uint32_t bl[2];
                    const char* q = sBl + n * ROWB + kb;
                    bl[0] = *(const uint32_t*)(q);
                    bl[1] = *(const uint32_t*)(q + 16);
#pragma unroll
                    for (int mt = 0; mt < 2; mt++)
                        MMA_F16(acc[mt][nt], ah[mt], bl);
                }
            }
        }

        if (c + 2 < nch) {
            __syncthreads();
            load_stage<NT>(pAh, pAl, pBh, pBl, (c + 2) * KC, ldAB,
                           smem + (c & 1) * STG, tid);
        }
    }

    // epilogue
    const int cq = (lane & 3) * 2;
    if (OUT == 0) {
        float* Cw = C + (size_t)blockIdx.z * sC
                      + (size_t)(m0 + wm * 32) * ldC + n0 + wn * 64;
#pragma unroll
        for (int mt = 0; mt < 2; mt++)
#pragma unroll
            for (int nt = 0; nt < 8; nt++) {
                float* p0 = Cw + (size_t)(mt * 16 + r) * ldC + nt * 8 + cq;
                float* p1 = p0 + 8 * (size_t)ldC;
                *(float2*)p0 = make_float2(acc[mt][nt][0] * oscale, acc[mt][nt][1] * oscale);
                *(float2*)p1 = make_float2(acc[mt][nt][2] * oscale, acc[mt][nt][3] * oscale);
            }
    } else if (OUT == 3) {
        // transposed per 4096-row batch: VT[b][n][m'] ; tile never straddles batch
        const int gm0 = m0 + wm * 32;
        const int b = gm0 >> 12;
        __half* D = Chi + (size_t)b * AA * SS;
#pragma unroll
        for (int mt = 0; mt < 2; mt++)
#pragma unroll
            for (int nt = 0; nt < 8; nt++) {
                const int col = n0 + wn * 64 + nt * 8 + cq;
                const int ms0 = (gm0 + mt * 16 + r) & 4095;
                const int ms1 = ms0 + 8;
                D[(size_t)col * SS + ms0]       = __float2half_rn(acc[mt][nt][0] * oscale);
                D[(size_t)(col + 1) * SS + ms0] = __float2half_rn(acc[mt][nt][1] * oscale);
                D[(size_t)col * SS + ms1]       = __float2half_rn(acc[mt][nt][2] * oscale);
                D[(size_t)(col + 1) * SS + ms1] = __float2half_rn(acc[mt][nt][3] * oscale);
            }
    } else {
        const size_t off = (size_t)blockIdx.z * sC
                         + (size_t)(m0 + wm * 32) * ldC + n0 + wn * 64;
        __half* Hw = Chi + off;
        __half* Lw = (OUT == 1) ? Clo + off : nullptr;
#pragma unroll
        for (int mt = 0; mt < 2; mt++)
#pragma unroll
            for (int nt = 0; nt < 8; nt++) {
                const size_t o0 = (size_t)(mt * 16 + r) * ldC + nt * 8 + cq;
                const size_t o1 = o0 + 8 * (size_t)ldC;
                float x0 = acc[mt][nt][0] * oscale, x1 = acc[mt][nt][1] * oscale;
                float x2 = acc[mt][nt][2] * oscale, x3 = acc[mt][nt][3] * oscale;
                __half h0 = __float2half_rn(x0), h1 = __float2half_rn(x1);
                __half h2 = __float2half_rn(x2), h3 = __float2half_rn(x3);
                *(__half2*)(Hw + o0) = __halves2half2(h0, h1);
                *(__half2*)(Hw + o1) = __halves2half2(h2, h3);
                if (OUT == 1) {
                    __half l0 = __float2half_rn(x0 - __half2float(h0));
                    __half l1 = __float2half_rn(x1 - __half2float(h1));
                    __half l2 = __float2half_rn(x2 - __half2float(h2));
                    __half l3 = __float2half_rn(x3 - __half2float(h3));
                    *(__half2*)(Lw + o0) = __halves2half2(l0, l1);
                    *(__half2*)(Lw + o1) = __halves2half2(l2, l3);
                }
            }
    }
}

// ---------------------------------------------------------------------------
// fp32 -> scaled fp16 hi/lo split (elementwise)
// ---------------------------------------------------------------------------
__global__ __launch_bounds__(256)
void split_plain(const float* __restrict__ in, __half* __restrict__ hi,
                 __half* __restrict__ lo, size_t n, float scale)
{
    size_t i = ((size_t)blockIdx.x * 256 + threadIdx.x) * 4;
    if (i >= n) return;
    float4 x = *(const float4*)(in + i);
    x.x *= scale; x.y *= scale; x.z *= scale; x.w *= scale;
    __half h0 = __float2half_rn(x.x), h1 = __float2half_rn(x.y);
    __half h2 = __float2half_rn(x.z), h3 = __float2half_rn(x.w);
    __half l0 = __float2half_rn(x.x - __half2float(h0));
    __half l1 = __float2half_rn(x.y - __half2float(h1));
    __half l2 = __float2half_rn(x.z - __half2float(h2));
    __half l3 = __float2half_rn(x.w - __half2float(h3));
    *(__half2*)(hi + i)     = __halves2half2(h0, h1);
    *(__half2*)(hi + i + 2) = __halves2half2(h2, h3);
    *(__half2*)(lo + i)     = __halves2half2(l0, l1);
    *(__half2*)(lo + i + 2) = __halves2half2(l2, l3);
}

// Wt split-K reduce: sum 4 partials, scale, split to fp16 hi/lo
__global__ __launch_bounds__(256)
void wt_reduce(const float* __restrict__ part, __half* __restrict__ hi,
               __half* __restrict__ lo, size_t n, float scale)
{
    size_t i = ((size_t)blockIdx.x * 256 + threadIdx.x) * 4;
    if (i >= n) return;
    float4 a = *(const float4*)(part + i);
    float4 b = *(const float4*)(part + n + i);
    float4 c = *(const float4*)(part + 2 * n + i);
    float4 d = *(const float4*)(part + 3 * n + i);
    float x0 = (a.x + b.x + c.x + d.x) * scale;
    float x1 = (a.y + b.y + c.y + d.y) * scale;
    float x2 = (a.z + b.z + c.z + d.z) * scale;
    float x3 = (a.w + b.w + c.w + d.w) * scale;
    __half h0 = __float2half_rn(x0), h1 = __float2half_rn(x1);
    __half h2 = __float2half_rn(x2), h3 = __float2half_rn(x3);
    *(__half2*)(hi + i)     = __halves2half2(h0, h1);
    *(__half2*)(hi + i + 2) = __halves2half2(h2, h3);
    __half l0 = __float2half_rn(x0 - __half2float(h0));
    __half l1 = __float2half_rn(x1 - __half2float(h1));
    __half l2 = __float2half_rn(x2 - __half2float(h2));
    __half l3 = __float2half_rn(x3 - __half2float(h3));
    *(__half2*)(lo + i)     = __halves2half2(l0, l1);
    *(__half2*)(lo + i + 2) = __halves2half2(l2, l3);
}

// fp32 [R,C] -> transposed, scaled fp16 hi only [C,R]
__global__ __launch_bounds__(256)
void transpose_hi16(const float* __restrict__ in, __half* __restrict__ hiT,
                    int R, int C, float scale)
{
    __shared__ float t[32][33];
    const int r0 = blockIdx.y * 32, c0 = blockIdx.x * 32;
    const int tx = threadIdx.x & 31, ty = threadIdx.x >> 5;
#pragma unroll
    for (int i = ty; i < 32; i += 8)
        t[i][tx] = in[(size_t)(r0 + i) * C + c0 + tx];
    __syncthreads();
#pragma unroll
    for (int i = ty; i < 32; i += 8)
        hiT[(size_t)(c0 + i) * R + r0 + tx] = __float2half_rn(t[tx][i] * scale);
}

// ---------------------------------------------------------------------------
// Row softmax (4096 cols), warp-shuffle reductions, write fp16 (hi only)
// ---------------------------------------------------------------------------
__global__ __launch_bounds__(256)
void softmax_f16(const float* __restrict__ S, __half* __restrict__ Ph)
{
    const size_t row = blockIdx.x;
    const float* p = S + row * (size_t)SS;
    const int tid = threadIdx.x;
    const int lane = tid & 31, warp = tid >> 5;
    __shared__ float wred[8];

    float4 v[4];
    float m = -INFINITY;
#pragma unroll
    for (int i = 0; i < 4; i++) {
        v[i] = ((const float4*)p)[tid + i * 256];
        m = fmaxf(m, fmaxf(fmaxf(v[i].x, v[i].y), fmaxf(v[i].z, v[i].w)));
    }
#pragma unroll
    for (int o = 16; o > 0; o >>= 1)
        m = fmaxf(m, __shfl_xor_sync(0xffffffffu, m, o));
    if (lane == 0) wred[warp] = m;
    __syncthreads();
    {
        float t = wred[lane & 7];
#pragma unroll
        for (int o = 4; o > 0; o >>= 1)
            t = fmaxf(t, __shfl_xor_sync(0xffffffffu, t, o, 8));
        m = t;   // every thread now has rowmax (lane&7 covers all 8 warps)
    }

    float sum = 0.0f;
#pragma unroll
    for (int i = 0; i < 4; i++) {
        v[i].x = __expf(v[i].x - m);
        v[i].y = __expf(v[i].y - m);
        v[i].z = __expf(v[i].z - m);
        v[i].w = __expf(v[i].w - m);
        sum += v[i].x + v[i].y + v[i].z + v[i].w;
    }
#pragma unroll
    for (int o = 16; o > 0; o >>= 1)
        sum += __shfl_xor_sync(0xffffffffu, sum, o);
    __syncthreads();   // protect wred reuse
    if (lane == 0) wred[warp] = sum;
    __syncthreads();
    {
        float t = wred[lane & 7];
#pragma unroll
        for (int o = 4; o > 0; o >>= 1)
            t += __shfl_xor_sync(0xffffffffu, t, o, 8);
        sum = t;
    }
    const float inv = 1.0f / sum;

#pragma unroll
    for (int i = 0; i < 4; i++) {
        size_t o = row * (size_t)SS + (size_t)(tid + i * 256) * 4;
        *(__half2*)(Ph + o)     = __halves2half2(__float2half_rn(v[i].x * inv),
                                                 __float2half_rn(v[i].y * inv));
        *(__half2*)(Ph + o + 2) = __halves2half2(__float2half_rn(v[i].z * inv),
                                                 __float2half_rn(v[i].w * inv));
    }
}

// ---------------------------------------------------------------------------
// kernel_launch — graph-capturable pipeline
//   S = X (Wq Wk^T) X^T  via  Wt = Wk Wq^T (split-K),  Y = X Wt,  S = Y X^T
// ---------------------------------------------------------------------------
extern "C" void kernel_launch(void* const* d_in, const int* in_sizes, int n_in,
                              void* d_out, int out_size)
{
    const float* X  = (const float*)d_in[0];
    const float* Wq = (const float*)d_in[1];
    const float* Wk = (const float*)d_in[2];
    const float* Wv = (const float*)d_in[3];
    float* out = (float*)d_out;

    float *Sc, *WtP;
    __half *Xhi, *Xlo, *Wq16h, *Wq16l, *Wk16h, *Wk16l, *WvTh;
    __half *Wth, *Wtl, *Yhi, *Ylo, *Vthi, *Phi;
    cudaGetSymbolAddress((void**)&Sc, g_S);
    cudaGetSymbolAddress((void**)&WtP, g_Wt_part);
    cudaGetSymbolAddress((void**)&Xhi, g_Xhi);
    cudaGetSymbolAddress((void**)&Xlo, g_Xlo);
    cudaGetSymbolAddress((void**)&Wq16h, g_Wq16h);
    cudaGetSymbolAddress((void**)&Wq16l, g_Wq16l);
    cudaGetSymbolAddress((void**)&Wk16h, g_Wk16h);
    cudaGetSymbolAddress((void**)&Wk16l, g_Wk16l);
    cudaGetSymbolAddress((void**)&WvTh, g_WvTh);
    cudaGetSymbolAddress((void**)&Wth, g_Wth);
    cudaGetSymbolAddress((void**)&Wtl, g_Wtl);
    cudaGetSymbolAddress((void**)&Yhi, g_Yhi);
    cudaGetSymbolAddress((void**)&Ylo, g_Ylo);
    cudaGetSymbolAddress((void**)&Vthi, g_Vthi);
    cudaGetSymbolAddress((void**)&Phi, g_Phi);

    const int SMEM_NT3 = 2 * 4 * TILE_T;   // 81920
    const int SMEM_NT1 = 2 * 2 * TILE_T;   // 40960
    cudaFuncSetAttribute(gemm_mma<3,0>, cudaFuncAttributeMaxDynamicSharedMemorySize, SMEM_NT3);
    cudaFuncSetAttribute(gemm_mma<3,1>, cudaFuncAttributeMaxDynamicSharedMemorySize, SMEM_NT3);
    cudaFuncSetAttribute(gemm_mma<1,0>, cudaFuncAttributeMaxDynamicSharedMemorySize, SMEM_NT1);
    cudaFuncSetAttribute(gemm_mma<1,3>, cudaFuncAttributeMaxDynamicSharedMemorySize, SMEM_NT1);

    const float INV16 = 1.0f / 16.0f;

    // 1) splits: X (unscaled), Wq/Wk (x16, no transpose), Wv^T hi (x16)
    split_plain<<<(MTOT * (size_t)DD) / 1024, 256>>>(X, Xhi, Xlo, (size_t)MTOT * DD, 1.0f);
    split_plain<<<((size_t)DD * AA) / 1024, 256>>>(Wq, Wq16h, Wq16l, (size_t)DD * AA, 16.0f);
    split_plain<<<((size_t)DD * AA) / 1024, 256>>>(Wk, Wk16h, Wk16l, (size_t)DD * AA, 16.0f);
    {
        dim3 g(AA / 32, DD / 32, 1);
        transpose_hi16<<<g, 256>>>(Wv, WvTh, DD, AA, 16.0f);
    }

    // 2) Wt = Wk Wq^T (3-term, split-K over 4 slices) -> partials -> reduce
    {
        dim3 g(DD / 128, DD / 128, 4);
        gemm_mma<3,0><<<g, 256, SMEM_NT3>>>(Wk16h, Wk16l, Wq16h, Wq16l,
                                            WtP, nullptr, nullptr,
                                            AA / 4, AA, DD,
                                            AA / 4, AA / 4, (long long)DD * DD, 1.0f);
        wt_reduce<<<((size_t)DD * DD) / 1024, 256>>>(WtP, Wth, Wtl,
                                                     (size_t)DD * DD, INV16);
    }

    // 3) V projection (1-term), epilogue writes V^T per batch directly
    {
        dim3 g(AA / 128, MTOT / 128, 1);
        gemm_mma<1,3><<<g, 256, SMEM_NT1>>>(Xhi, nullptr, WvTh, nullptr,
                                            nullptr, Vthi, nullptr,
                                            DD, DD, 0, 0, 0, 0, INV16);
    }

    // 4) Y = X @ Wt (3-term): raw 16*Y; store Y hi/lo
    {
        dim3 g(DD / 128, MTOT / 128, 1);
        gemm_mma<3,1><<<g, 256, SMEM_NT3>>>(Xhi, Xlo, Wth, Wtl,
                                            nullptr, Yhi, Ylo,
                                            DD, DD, DD, 0, 0, 0, INV16);
    }

    // 5) scores (3-term): S = Y @ X^T per batch
    {
        dim3 g(SS / 128, SS / 128, BB);
        gemm_mma<3,0><<<g, 256, SMEM_NT3>>>(Yhi, Ylo, Xhi, Xlo, Sc, nullptr, nullptr,
                                            DD, DD, SS,
                                            (long long)SS * DD, (long long)SS * DD,
                                            (long long)SS * SS, 1.0f);
    }

    // 6) softmax -> fp16 P (hi only)
    softmax_f16<<<BB * SS, 256>>>(Sc, Phi);

    // 7) output (1-term): O = P @ V per batch
    {
        dim3 g(AA / 128, SS / 128, BB);
        gemm_mma<1,0><<<g, 256, SMEM_NT1>>>(Phi, nullptr, Vthi, nullptr,
                                            out, nullptr, nullptr,
                                            SS, SS, AA,
                                            (long long)SS * SS, (long long)AA * SS,
                                            (long long)SS * AA, 1.0f);
    }
}